// round 1
// baseline (speedup 1.0000x reference)
#include <cuda_runtime.h>

#define SQ 8192
#define DIMN 512
#define SCALE 0.04419417382415922f  // 1/sqrt(512)

// Scratch for Q, K, V projections (48 MB total, zero-init device globals)
__device__ float g_q[SQ * DIMN];
__device__ float g_k[SQ * DIMN];
__device__ float g_v[SQ * DIMN];

// ---------------------------------------------------------------------------
// Kernel 1: fused QKV projection.  C = x @ W^T + b  (NT GEMM, M=8192,N=512,K=512)
// blockIdx.z selects Q/K/V. 128x128 tile, BK=16, 256 threads, 8x8 per thread.
// ---------------------------------------------------------------------------
__global__ __launch_bounds__(256) void qkv_kernel(
    const float* __restrict__ x,
    const float* __restrict__ Wq, const float* __restrict__ bq,
    const float* __restrict__ Wk, const float* __restrict__ bk,
    const float* __restrict__ Wv, const float* __restrict__ bv)
{
    const float* W; const float* bias; float* C;
    if (blockIdx.z == 0)      { W = Wq; bias = bq; C = g_q; }
    else if (blockIdx.z == 1) { W = Wk; bias = bk; C = g_k; }
    else                      { W = Wv; bias = bv; C = g_v; }

    __shared__ float As[16][128];
    __shared__ float Bs[16][128];

    const int tid = threadIdx.x;
    const int tx = tid & 15;
    const int ty = tid >> 4;
    const int row0 = blockIdx.y * 128;
    const int col0 = blockIdx.x * 128;

    float acc[8][8];
    #pragma unroll
    for (int i = 0; i < 8; i++)
        #pragma unroll
        for (int j = 0; j < 8; j++) acc[i][j] = 0.f;

    const int lr = tid >> 2;         // 0..63
    const int lk = (tid & 3) * 4;    // 0,4,8,12

    for (int k0 = 0; k0 < DIMN; k0 += 16) {
        #pragma unroll
        for (int h = 0; h < 2; h++) {
            int r = lr + h * 64;
            float4 a = *(const float4*)(x + (size_t)(row0 + r) * DIMN + k0 + lk);
            As[lk + 0][r] = a.x; As[lk + 1][r] = a.y; As[lk + 2][r] = a.z; As[lk + 3][r] = a.w;
            float4 b = *(const float4*)(W + (size_t)(col0 + r) * DIMN + k0 + lk);
            Bs[lk + 0][r] = b.x; Bs[lk + 1][r] = b.y; Bs[lk + 2][r] = b.z; Bs[lk + 3][r] = b.w;
        }
        __syncthreads();
        #pragma unroll
        for (int kk = 0; kk < 16; kk++) {
            float a[8], b[8];
            *(float4*)&a[0] = *(const float4*)&As[kk][ty * 8];
            *(float4*)&a[4] = *(const float4*)&As[kk][ty * 8 + 4];
            *(float4*)&b[0] = *(const float4*)&Bs[kk][tx * 8];
            *(float4*)&b[4] = *(const float4*)&Bs[kk][tx * 8 + 4];
            #pragma unroll
            for (int i = 0; i < 8; i++)
                #pragma unroll
                for (int j = 0; j < 8; j++)
                    acc[i][j] += a[i] * b[j];
        }
        __syncthreads();
    }

    #pragma unroll
    for (int i = 0; i < 8; i++) {
        int r = row0 + ty * 8 + i;
        #pragma unroll
        for (int j = 0; j < 8; j += 4) {
            int c = col0 + tx * 8 + j;
            float4 v;
            v.x = acc[i][j + 0] + bias[c + 0];
            v.y = acc[i][j + 1] + bias[c + 1];
            v.z = acc[i][j + 2] + bias[c + 2];
            v.w = acc[i][j + 3] + bias[c + 3];
            *(float4*)(C + (size_t)r * DIMN + c) = v;
        }
    }
}

// ---------------------------------------------------------------------------
// Kernel 2: scores = (Q @ K^T) * scale, written RAW into the attn region.
// Strict upper-triangle tiles: write exact 0 (these are the final weights).
// Diagonal tile: invalid (col>row) entries write 0 and are never rewritten.
// ---------------------------------------------------------------------------
__global__ __launch_bounds__(256) void scores_kernel(float* __restrict__ attn)
{
    const int bi = blockIdx.y;   // row tile
    const int bj = blockIdx.x;   // col tile
    const int tid = threadIdx.x;
    const int row0 = bi * 128;
    const int col0 = bj * 128;

    if (bj > bi) {
        float4 z = make_float4(0.f, 0.f, 0.f, 0.f);
        #pragma unroll 4
        for (int idx = tid; idx < 128 * 32; idx += 256) {
            int r = idx >> 5;
            int c = (idx & 31) << 2;
            *(float4*)(attn + (size_t)(row0 + r) * SQ + col0 + c) = z;
        }
        return;
    }

    __shared__ float As[16][128];
    __shared__ float Bs[16][128];
    const int tx = tid & 15;
    const int ty = tid >> 4;

    float acc[8][8];
    #pragma unroll
    for (int i = 0; i < 8; i++)
        #pragma unroll
        for (int j = 0; j < 8; j++) acc[i][j] = 0.f;

    const int lr = tid >> 2;
    const int lk = (tid & 3) * 4;

    for (int k0 = 0; k0 < DIMN; k0 += 16) {
        #pragma unroll
        for (int h = 0; h < 2; h++) {
            int r = lr + h * 64;
            float4 a = *(const float4*)(g_q + (size_t)(row0 + r) * DIMN + k0 + lk);
            As[lk + 0][r] = a.x; As[lk + 1][r] = a.y; As[lk + 2][r] = a.z; As[lk + 3][r] = a.w;
            float4 b = *(const float4*)(g_k + (size_t)(col0 + r) * DIMN + k0 + lk);
            Bs[lk + 0][r] = b.x; Bs[lk + 1][r] = b.y; Bs[lk + 2][r] = b.z; Bs[lk + 3][r] = b.w;
        }
        __syncthreads();
        #pragma unroll
        for (int kk = 0; kk < 16; kk++) {
            float a[8], b[8];
            *(float4*)&a[0] = *(const float4*)&As[kk][ty * 8];
            *(float4*)&a[4] = *(const float4*)&As[kk][ty * 8 + 4];
            *(float4*)&b[0] = *(const float4*)&Bs[kk][tx * 8];
            *(float4*)&b[4] = *(const float4*)&Bs[kk][tx * 8 + 4];
            #pragma unroll
            for (int i = 0; i < 8; i++)
                #pragma unroll
                for (int j = 0; j < 8; j++)
                    acc[i][j] += a[i] * b[j];
        }
        __syncthreads();
    }

    const bool diag = (bi == bj);
    #pragma unroll
    for (int i = 0; i < 8; i++) {
        int r = row0 + ty * 8 + i;
        #pragma unroll
        for (int j = 0; j < 8; j++) {
            int c = col0 + tx * 8 + j;
            float v = acc[i][j] * SCALE;
            if (diag && c > r) v = 0.f;   // final weight there is exactly 0
            attn[(size_t)r * SQ + c] = v;
        }
    }
}

// ---------------------------------------------------------------------------
// Kernel 3: per-row causal softmax, in place. One CTA per row, row cached in smem.
// Only touches columns [0, i]; columns > i already hold the final 0 weights.
// ---------------------------------------------------------------------------
__global__ __launch_bounds__(256) void softmax_kernel(float* __restrict__ attn)
{
    __shared__ float buf[SQ];     // 32 KB, max row length
    __shared__ float red[32];
    __shared__ float s_bcast;

    const int i = blockIdx.x;
    const int L = i + 1;
    float* row = attn + (size_t)i * SQ;
    const int tid = threadIdx.x;

    float mx = -3.4e38f;
    for (int j = tid; j < L; j += 256) {
        float s = row[j];
        buf[j] = s;
        mx = fmaxf(mx, s);
    }
    #pragma unroll
    for (int o = 16; o; o >>= 1) mx = fmaxf(mx, __shfl_xor_sync(0xffffffffu, mx, o));
    if ((tid & 31) == 0) red[tid >> 5] = mx;
    __syncthreads();
    if (tid < 32) {
        float v = (tid < 8) ? red[tid] : -3.4e38f;
        #pragma unroll
        for (int o = 4; o; o >>= 1) v = fmaxf(v, __shfl_xor_sync(0xffffffffu, v, o));
        if (tid == 0) s_bcast = v;
    }
    __syncthreads();
    mx = s_bcast;

    float sum = 0.f;
    for (int j = tid; j < L; j += 256) {
        float e = __expf(buf[j] - mx);
        buf[j] = e;
        sum += e;
    }
    #pragma unroll
    for (int o = 16; o; o >>= 1) sum += __shfl_xor_sync(0xffffffffu, sum, o);
    __syncthreads();            // red[] reuse
    if ((tid & 31) == 0) red[tid >> 5] = sum;
    __syncthreads();
    if (tid < 32) {
        float v = (tid < 8) ? red[tid] : 0.f;
        #pragma unroll
        for (int o = 4; o; o >>= 1) v += __shfl_xor_sync(0xffffffffu, v, o);
        if (tid == 0) s_bcast = 1.f / v;
    }
    __syncthreads();
    const float inv = s_bcast;

    for (int j = tid; j < L; j += 256) row[j] = buf[j] * inv;
}

// ---------------------------------------------------------------------------
// Kernel 4: output = attn @ V  (NN GEMM, M=8192, N=512, K bounded by causal mask)
// K-loop only runs over the lower-triangle range (kmax = (bm+1)*128).
// Heavy row-tiles scheduled first (flat id reversed) to shrink the wave tail.
// ---------------------------------------------------------------------------
__global__ __launch_bounds__(256) void av_kernel(const float* __restrict__ attn,
                                                 float* __restrict__ out)
{
    const int flat = blockIdx.x;          // 0..255
    const int bm = 63 - (flat >> 2);      // heaviest tiles first
    const int bn = flat & 3;
    const int row0 = bm * 128;
    const int col0 = bn * 128;
    const int kmax = (bm + 1) * 128;

    __shared__ float As[16][128];
    __shared__ float Bs[16][128];
    const int tid = threadIdx.x;
    const int tx = tid & 15;
    const int ty = tid >> 4;

    float acc[8][8];
    #pragma unroll
    for (int i = 0; i < 8; i++)
        #pragma unroll
        for (int j = 0; j < 8; j++) acc[i][j] = 0.f;

    const int lr = tid >> 2;
    const int lk = (tid & 3) * 4;

    for (int k0 = 0; k0 < kmax; k0 += 16) {
        #pragma unroll
        for (int h = 0; h < 2; h++) {
            int r = lr + h * 64;
            float4 a = *(const float4*)(attn + (size_t)(row0 + r) * SQ + k0 + lk);
            As[lk + 0][r] = a.x; As[lk + 1][r] = a.y; As[lk + 2][r] = a.z; As[lk + 3][r] = a.w;
        }
        #pragma unroll
        for (int h = 0; h < 2; h++) {
            int idx = tid + h * 256;
            int r = idx >> 5;               // 0..15 (k within tile)
            int c = (idx & 31) << 2;        // 0..124 (n within tile)
            *(float4*)&Bs[r][c] =
                *(const float4*)(g_v + (size_t)(k0 + r) * DIMN + col0 + c);
        }
        __syncthreads();
        #pragma unroll
        for (int kk = 0; kk < 16; kk++) {
            float a[8], b[8];
            *(float4*)&a[0] = *(const float4*)&As[kk][ty * 8];
            *(float4*)&a[4] = *(const float4*)&As[kk][ty * 8 + 4];
            *(float4*)&b[0] = *(const float4*)&Bs[kk][tx * 8];
            *(float4*)&b[4] = *(const float4*)&Bs[kk][tx * 8 + 4];
            #pragma unroll
            for (int i = 0; i < 8; i++)
                #pragma unroll
                for (int j = 0; j < 8; j++)
                    acc[i][j] += a[i] * b[j];
        }
        __syncthreads();
    }

    #pragma unroll
    for (int i = 0; i < 8; i++) {
        int r = row0 + ty * 8 + i;
        #pragma unroll
        for (int j = 0; j < 8; j += 4) {
            int c = col0 + tx * 8 + j;
            float4 v;
            v.x = acc[i][j + 0];
            v.y = acc[i][j + 1];
            v.z = acc[i][j + 2];
            v.w = acc[i][j + 3];
            *(float4*)(out + (size_t)r * DIMN + c) = v;
        }
    }
}

// ---------------------------------------------------------------------------
extern "C" void kernel_launch(void* const* d_in, const int* in_sizes, int n_in,
                              void* d_out, int out_size)
{
    const float* x  = (const float*)d_in[0];
    const float* Wq = (const float*)d_in[1];
    const float* bq = (const float*)d_in[2];
    const float* Wk = (const float*)d_in[3];
    const float* bk = (const float*)d_in[4];
    const float* Wv = (const float*)d_in[5];
    const float* bv = (const float*)d_in[6];

    float* out  = (float*)d_out;                    // [S, D]  (tuple element 0)
    float* attn = out + (size_t)SQ * DIMN;          // [S, S]  (tuple element 1)

    dim3 g_qkv(DIMN / 128, SQ / 128, 3);            // 4 x 64 x 3
    qkv_kernel<<<g_qkv, 256>>>(x, Wq, bq, Wk, bk, Wv, bv);

    dim3 g_sc(SQ / 128, SQ / 128);                  // 64 x 64
    scores_kernel<<<g_sc, 256>>>(attn);

    softmax_kernel<<<SQ, 256>>>(attn);

    av_kernel<<<(SQ / 128) * (DIMN / 128), 256>>>(attn, out);
}

// round 3
// speedup vs baseline: 2.2226x; 2.2226x over previous
#include <cuda_runtime.h>
#include <cuda_bf16.h>
#include <cstdint>

#define SQ 8192
#define DIMN 512
#define SCALE 0.04419417382415922f  // 1/sqrt(512)
#define KCHUNK 32                   // k per pipeline stage (bf16)

// bf16 split-2 operand storage (zero-initialized device globals)
__device__ __nv_bfloat16 g_xh[SQ * DIMN],  g_xl[SQ * DIMN];
__device__ __nv_bfloat16 g_wh[3 * DIMN * DIMN], g_wl[3 * DIMN * DIMN];
__device__ __nv_bfloat16 g_qh[SQ * DIMN],  g_ql[SQ * DIMN];
__device__ __nv_bfloat16 g_kh[SQ * DIMN],  g_kl[SQ * DIMN];
__device__ __nv_bfloat16 g_vth[DIMN * SQ], g_vtl[DIMN * SQ];   // V^T: [512, 8192]
__device__ __nv_bfloat16 g_ah[(size_t)SQ * SQ], g_al[(size_t)SQ * SQ];  // attn split

// ---------------------------------------------------------------------------
// PTX helpers (base-ISA only: ldmatrix / mma.sync / cp.async — no tcgen05)
// ---------------------------------------------------------------------------
__device__ __forceinline__ uint32_t smem_u32(const void* p) {
    uint32_t a;
    asm("{ .reg .u64 t; cvta.to.shared.u64 t, %1; cvt.u32.u64 %0, t; }" : "=r"(a) : "l"(p));
    return a;
}
__device__ __forceinline__ void cp16(uint32_t dst, const void* src) {
    asm volatile("cp.async.cg.shared.global [%0], [%1], 16;" :: "r"(dst), "l"(src));
}
__device__ __forceinline__ void cp_commit() { asm volatile("cp.async.commit_group;" ::: "memory"); }
__device__ __forceinline__ void cp_wait1()  { asm volatile("cp.async.wait_group 1;" ::: "memory"); }
__device__ __forceinline__ void cp_wait0()  { asm volatile("cp.async.wait_group 0;" ::: "memory"); }
__device__ __forceinline__ void ldm_x4(uint32_t* r, uint32_t addr) {
    asm volatile("ldmatrix.sync.aligned.m8n8.x4.shared.b16 {%0,%1,%2,%3}, [%4];"
        : "=r"(r[0]), "=r"(r[1]), "=r"(r[2]), "=r"(r[3]) : "r"(addr));
}
__device__ __forceinline__ void mma_bf16(float* d, const uint32_t* a, const uint32_t* b) {
    asm volatile("mma.sync.aligned.m16n8k16.row.col.f32.bf16.bf16.f32 "
        "{%0,%1,%2,%3}, {%4,%5,%6,%7}, {%8,%9}, {%0,%1,%2,%3};"
        : "+f"(d[0]), "+f"(d[1]), "+f"(d[2]), "+f"(d[3])
        : "r"(a[0]), "r"(a[1]), "r"(a[2]), "r"(a[3]), "r"(b[0]), "r"(b[1]));
}
__device__ __forceinline__ void split2(float v, __nv_bfloat16& h, __nv_bfloat16& l) {
    h = __float2bfloat16(v);
    l = __float2bfloat16(v - __bfloat162float(h));
}

// Swizzled smem byte offset for (row, 16B-chunk) within a 128x32-bf16 tile (64B rows)
__device__ __forceinline__ uint32_t sw_off(int r, int c) {
    return (uint32_t)(r * 64 + ((c ^ ((r >> 1) & 3)) << 4));
}

// ---------------------------------------------------------------------------
// Issue one 32-wide K chunk (Ah,Al,Bh,Bl: 128 rows x 32 bf16 each) via cp.async
// 256 threads: thread t loads rows t/2, two 16B chunks.
// ---------------------------------------------------------------------------
__device__ __forceinline__ void issue_chunk(
    uint32_t sb,
    const __nv_bfloat16* __restrict__ Ah, const __nv_bfloat16* __restrict__ Al, int sA,
    const __nv_bfloat16* __restrict__ Bh, const __nv_bfloat16* __restrict__ Bl, int sB,
    int c, int tid)
{
    const int r  = tid >> 1;
    const int c0 = (tid & 1) * 2;
    const size_t ko = (size_t)c * KCHUNK + c0 * 8;
    const uint32_t o1 = sw_off(r, c0);
    const uint32_t o2 = sw_off(r, c0 + 1);
    const size_t ra = (size_t)r * sA + ko;
    const size_t rb = (size_t)r * sB + ko;
    cp16(sb +     0 + o1, Ah + ra);     cp16(sb +     0 + o2, Ah + ra + 8);
    cp16(sb +  8192 + o1, Al + ra);     cp16(sb +  8192 + o2, Al + ra + 8);
    cp16(sb + 16384 + o1, Bh + rb);     cp16(sb + 16384 + o2, Bh + rb + 8);
    cp16(sb + 24576 + o1, Bl + rb);     cp16(sb + 24576 + o2, Bl + rb + 8);
}

// ---------------------------------------------------------------------------
// Mainloop: acc[4][4][4] += 3-term split MMA over nchunks K-chunks.
// CTA = 256 threads = 8 warps (2 x 4). Warp tile 64x32.
// ---------------------------------------------------------------------------
__device__ __forceinline__ void run_gemm(
    const __nv_bfloat16* __restrict__ Ah, const __nv_bfloat16* __restrict__ Al, int sA,
    const __nv_bfloat16* __restrict__ Bh, const __nv_bfloat16* __restrict__ Bl, int sB,
    int nchunks, uint32_t sbase, float acc[4][4][4])
{
    const int tid  = threadIdx.x;
    const int wid  = tid >> 5;
    const int lane = tid & 31;
    const int wm = (wid >> 2) * 64;   // warp row offset in CTA tile
    const int wn = (wid & 3) * 32;    // warp col offset
    const int lr = lane & 15;         // ldmatrix row-within-16
    const int lc = lane >> 4;         // ldmatrix k8-chunk select (0/1)

    issue_chunk(sbase, Ah, Al, sA, Bh, Bl, sB, 0, tid);
    cp_commit();

    for (int c = 0; c < nchunks; c++) {
        const uint32_t st = sbase + (uint32_t)(c & 1) * 32768u;
        if (c + 1 < nchunks) {
            issue_chunk(sbase + (uint32_t)((c + 1) & 1) * 32768u,
                        Ah + (size_t)(c + 1) * KCHUNK, Al + (size_t)(c + 1) * KCHUNK, sA,
                        Bh + (size_t)(c + 1) * KCHUNK, Bl + (size_t)(c + 1) * KCHUNK, sB,
                        0, tid);
            cp_commit();
            cp_wait1();
        } else {
            cp_wait0();
        }
        __syncthreads();

        #pragma unroll
        for (int ks = 0; ks < 2; ks++) {
            const int kch = 2 * ks + lc;
            uint32_t aH[4][4], aL[4][4], bH[4][2], bL[4][2];
            #pragma unroll
            for (int i = 0; i < 4; i++) {
                int r = wm + i * 16 + lr;
                uint32_t off = sw_off(r, kch);
                ldm_x4(aH[i], st +    0 + off);
                ldm_x4(aL[i], st + 8192 + off);
            }
            #pragma unroll
            for (int j2 = 0; j2 < 2; j2++) {
                int r = wn + j2 * 16 + lr;
                uint32_t off = sw_off(r, kch);
                uint32_t t4[4];
                ldm_x4(t4, st + 16384 + off);
                bH[2*j2][0] = t4[0]; bH[2*j2+1][0] = t4[1];
                bH[2*j2][1] = t4[2]; bH[2*j2+1][1] = t4[3];
                ldm_x4(t4, st + 24576 + off);
                bL[2*j2][0] = t4[0]; bL[2*j2+1][0] = t4[1];
                bL[2*j2][1] = t4[2]; bL[2*j2+1][1] = t4[3];
            }
            #pragma unroll
            for (int i = 0; i < 4; i++)
                #pragma unroll
                for (int j = 0; j < 4; j++) {
                    mma_bf16(acc[i][j], aH[i], bH[j]);
                    mma_bf16(acc[i][j], aH[i], bL[j]);
                    mma_bf16(acc[i][j], aL[i], bH[j]);
                }
        }
        __syncthreads();
    }
}

// Accumulator element coords: tile (i,j), reg r ->
//   row = wm + i*16 + (lane>>2) + 8*(r>>1),  col = wn + j*8 + 2*(lane&3) + (r&1)

// ---------------------------------------------------------------------------
// Kernel: split x and W into bf16 hi/lo
// ---------------------------------------------------------------------------
__global__ __launch_bounds__(256) void conv_kernel(
    const float* __restrict__ x, const float* __restrict__ Wq,
    const float* __restrict__ Wk, const float* __restrict__ Wv)
{
    int idx = blockIdx.x * 256 + threadIdx.x;
    split2(x[idx], g_xh[idx], g_xl[idx]);
    if (idx < DIMN * DIMN) {
        split2(Wq[idx], g_wh[idx],                   g_wl[idx]);
        split2(Wk[idx], g_wh[DIMN * DIMN + idx],     g_wl[DIMN * DIMN + idx]);
        split2(Wv[idx], g_wh[2 * DIMN * DIMN + idx], g_wl[2 * DIMN * DIMN + idx]);
    }
}

// ---------------------------------------------------------------------------
// Kernel: QKV projection. grid (4, 64, 3). Emits q/k hi-lo and V^T hi-lo.
// ---------------------------------------------------------------------------
__global__ __launch_bounds__(256) void qkv_mma_kernel(
    const float* __restrict__ bq, const float* __restrict__ bk, const float* __restrict__ bv)
{
    extern __shared__ __align__(16) char dsm[];
    uint32_t sbase = smem_u32(dsm);

    const int z = blockIdx.z;
    const int row0 = blockIdx.y * 128;
    const int col0 = blockIdx.x * 128;
    const float* bias = (z == 0) ? bq : (z == 1) ? bk : bv;

    float acc[4][4][4];
    #pragma unroll
    for (int i = 0; i < 4; i++)
        #pragma unroll
        for (int j = 0; j < 4; j++)
            #pragma unroll
            for (int r = 0; r < 4; r++) acc[i][j][r] = 0.f;

    run_gemm(g_xh + (size_t)row0 * DIMN, g_xl + (size_t)row0 * DIMN, DIMN,
             g_wh + (size_t)z * DIMN * DIMN + (size_t)col0 * DIMN,
             g_wl + (size_t)z * DIMN * DIMN + (size_t)col0 * DIMN, DIMN,
             DIMN / KCHUNK, sbase, acc);

    const int tid = threadIdx.x, wid = tid >> 5, lane = tid & 31;
    const int wm = (wid >> 2) * 64, wn = (wid & 3) * 32;
    #pragma unroll
    for (int i = 0; i < 4; i++)
        #pragma unroll
        for (int j = 0; j < 4; j++)
            #pragma unroll
            for (int r = 0; r < 4; r++) {
                int rr = row0 + wm + i * 16 + (lane >> 2) + 8 * (r >> 1);
                int cc = col0 + wn + j * 8 + 2 * (lane & 3) + (r & 1);
                float v = acc[i][j][r] + bias[cc];
                if (z == 0)      split2(v, g_qh[(size_t)rr * DIMN + cc], g_ql[(size_t)rr * DIMN + cc]);
                else if (z == 1) split2(v, g_kh[(size_t)rr * DIMN + cc], g_kl[(size_t)rr * DIMN + cc]);
                else             split2(v, g_vth[(size_t)cc * SQ + rr], g_vtl[(size_t)cc * SQ + rr]);
            }
}

// ---------------------------------------------------------------------------
// Kernel: raw causal scores. 2080 lower-triangle tiles, 1D grid.
// ---------------------------------------------------------------------------
__global__ __launch_bounds__(256) void scores_mma_kernel(float* __restrict__ attn)
{
    extern __shared__ __align__(16) char dsm[];
    uint32_t sbase = smem_u32(dsm);

    int t = blockIdx.x;
    int bi = (int)((sqrtf(8.f * t + 1.f) - 1.f) * 0.5f);
    while ((bi + 1) * (bi + 2) / 2 <= t) bi++;
    while (bi * (bi + 1) / 2 > t) bi--;
    int bj = t - bi * (bi + 1) / 2;
    const int row0 = bi * 128, col0 = bj * 128;

    float acc[4][4][4];
    #pragma unroll
    for (int i = 0; i < 4; i++)
        #pragma unroll
        for (int j = 0; j < 4; j++)
            #pragma unroll
            for (int r = 0; r < 4; r++) acc[i][j][r] = 0.f;

    run_gemm(g_qh + (size_t)row0 * DIMN, g_ql + (size_t)row0 * DIMN, DIMN,
             g_kh + (size_t)col0 * DIMN, g_kl + (size_t)col0 * DIMN, DIMN,
             DIMN / KCHUNK, sbase, acc);

    const int tid = threadIdx.x, wid = tid >> 5, lane = tid & 31;
    const int wm = (wid >> 2) * 64, wn = (wid & 3) * 32;
    const bool diag = (bi == bj);
    #pragma unroll
    for (int i = 0; i < 4; i++)
        #pragma unroll
        for (int j = 0; j < 4; j++)
            #pragma unroll
            for (int rh = 0; rh < 2; rh++) {
                int rr = row0 + wm + i * 16 + (lane >> 2) + 8 * rh;
                int cc = col0 + wn + j * 8 + 2 * (lane & 3);
                float2 v;
                v.x = acc[i][j][2 * rh + 0] * SCALE;
                v.y = acc[i][j][2 * rh + 1] * SCALE;
                if (diag) {
                    if (cc + 0 > rr) v.x = 0.f;
                    if (cc + 1 > rr) v.y = 0.f;
                }
                *(float2*)(attn + (size_t)rr * SQ + cc) = v;
            }
}

// ---------------------------------------------------------------------------
// Kernel: zero-fill strict upper triangle of attn (final weights there are 0)
// ---------------------------------------------------------------------------
__global__ __launch_bounds__(256) void zerofill_kernel(float* __restrict__ attn)
{
    const int bi = blockIdx.y, bj = blockIdx.x;
    if (bj <= bi) return;
    const int row0 = bi * 128, col0 = bj * 128;
    float4 z = make_float4(0.f, 0.f, 0.f, 0.f);
    #pragma unroll 4
    for (int idx = threadIdx.x; idx < 128 * 32; idx += 256) {
        int r = idx >> 5, c = (idx & 31) << 2;
        *(float4*)(attn + (size_t)(row0 + r) * SQ + col0 + c) = z;
    }
}

// ---------------------------------------------------------------------------
// Kernel: causal softmax in place + emit bf16 hi/lo weights for AV GEMM
// ---------------------------------------------------------------------------
__global__ __launch_bounds__(256) void softmax_kernel(float* __restrict__ attn)
{
    __shared__ float buf[SQ];
    __shared__ float red[32];
    __shared__ float s_bcast;

    const int i = blockIdx.x;
    const int L = i + 1;
    float* row = attn + (size_t)i * SQ;
    const int tid = threadIdx.x;

    float mx = -3.4e38f;
    for (int j = tid; j < L; j += 256) {
        float s = row[j];
        buf[j] = s;
        mx = fmaxf(mx, s);
    }
    #pragma unroll
    for (int o = 16; o; o >>= 1) mx = fmaxf(mx, __shfl_xor_sync(0xffffffffu, mx, o));
    if ((tid & 31) == 0) red[tid >> 5] = mx;
    __syncthreads();
    if (tid < 32) {
        float v = (tid < 8) ? red[tid] : -3.4e38f;
        #pragma unroll
        for (int o = 4; o; o >>= 1) v = fmaxf(v, __shfl_xor_sync(0xffffffffu, v, o));
        if (tid == 0) s_bcast = v;
    }
    __syncthreads();
    mx = s_bcast;

    float sum = 0.f;
    for (int j = tid; j < L; j += 256) {
        float e = __expf(buf[j] - mx);
        buf[j] = e;
        sum += e;
    }
    #pragma unroll
    for (int o = 16; o; o >>= 1) sum += __shfl_xor_sync(0xffffffffu, sum, o);
    __syncthreads();
    if ((tid & 31) == 0) red[tid >> 5] = sum;
    __syncthreads();
    if (tid < 32) {
        float v = (tid < 8) ? red[tid] : 0.f;
        #pragma unroll
        for (int o = 4; o; o >>= 1) v += __shfl_xor_sync(0xffffffffu, v, o);
        if (tid == 0) s_bcast = 1.f / v;
    }
    __syncthreads();
    const float inv = s_bcast;

    for (int j = tid; j < L; j += 256) {
        float w = buf[j] * inv;
        row[j] = w;
        __nv_bfloat16 h, l;
        split2(w, h, l);
        g_ah[(size_t)i * SQ + j] = h;
        g_al[(size_t)i * SQ + j] = l;
    }
}

// ---------------------------------------------------------------------------
// Kernel: output = attn @ V^T-stored-V. K bounded by causal range; heavy first.
// ---------------------------------------------------------------------------
__global__ __launch_bounds__(256) void av_mma_kernel(float* __restrict__ out)
{
    extern __shared__ __align__(16) char dsm[];
    uint32_t sbase = smem_u32(dsm);

    const int flat = blockIdx.x;            // 256 tiles
    const int bm = 63 - (flat >> 2);        // heaviest first
    const int bn = flat & 3;
    const int row0 = bm * 128, col0 = bn * 128;
    const int nchunks = (bm + 1) * (128 / KCHUNK);

    float acc[4][4][4];
    #pragma unroll
    for (int i = 0; i < 4; i++)
        #pragma unroll
        for (int j = 0; j < 4; j++)
            #pragma unroll
            for (int r = 0; r < 4; r++) acc[i][j][r] = 0.f;

    run_gemm(g_ah + (size_t)row0 * SQ, g_al + (size_t)row0 * SQ, SQ,
             g_vth + (size_t)col0 * SQ, g_vtl + (size_t)col0 * SQ, SQ,
             nchunks, sbase, acc);

    const int tid = threadIdx.x, wid = tid >> 5, lane = tid & 31;
    const int wm = (wid >> 2) * 64, wn = (wid & 3) * 32;
    #pragma unroll
    for (int i = 0; i < 4; i++)
        #pragma unroll
        for (int j = 0; j < 4; j++)
            #pragma unroll
            for (int rh = 0; rh < 2; rh++) {
                int rr = row0 + wm + i * 16 + (lane >> 2) + 8 * rh;
                int cc = col0 + wn + j * 8 + 2 * (lane & 3);
                float2 v;
                v.x = acc[i][j][2 * rh + 0];
                v.y = acc[i][j][2 * rh + 1];
                *(float2*)(out + (size_t)rr * DIMN + cc) = v;
            }
}

// ---------------------------------------------------------------------------
extern "C" void kernel_launch(void* const* d_in, const int* in_sizes, int n_in,
                              void* d_out, int out_size)
{
    const float* x  = (const float*)d_in[0];
    const float* Wq = (const float*)d_in[1];
    const float* bq = (const float*)d_in[2];
    const float* Wk = (const float*)d_in[3];
    const float* bk = (const float*)d_in[4];
    const float* Wv = (const float*)d_in[5];
    const float* bv = (const float*)d_in[6];

    float* out  = (float*)d_out;                 // [S, D]
    float* attn = out + (size_t)SQ * DIMN;       // [S, S]

    const int SMEM_BYTES = 65536;                // 2 stages x 32KB
    cudaFuncSetAttribute(qkv_mma_kernel,    cudaFuncAttributeMaxDynamicSharedMemorySize, SMEM_BYTES);
    cudaFuncSetAttribute(scores_mma_kernel, cudaFuncAttributeMaxDynamicSharedMemorySize, SMEM_BYTES);
    cudaFuncSetAttribute(av_mma_kernel,     cudaFuncAttributeMaxDynamicSharedMemorySize, SMEM_BYTES);

    conv_kernel<<<(SQ * DIMN) / 256, 256>>>(x, Wq, Wk, Wv);

    dim3 g_qkv(DIMN / 128, SQ / 128, 3);
    qkv_mma_kernel<<<g_qkv, 256, SMEM_BYTES>>>(bq, bk, bv);

    dim3 g_zf(SQ / 128, SQ / 128);
    zerofill_kernel<<<g_zf, 256>>>(attn);

    scores_mma_kernel<<<2080, 256, SMEM_BYTES>>>(attn);

    softmax_kernel<<<SQ, 256>>>(attn);

    av_mma_kernel<<<256, 256, SMEM_BYTES>>>(out);
}

// round 4
// speedup vs baseline: 2.5993x; 1.1695x over previous
#include <cuda_runtime.h>
#include <cuda_bf16.h>
#include <cstdint>

#define SQ 8192
#define DIMN 512
#define SCALE 0.04419417382415922f  // 1/sqrt(512)
#define KCHUNK 32                   // k per pipeline stage (bf16)
#define STAGE_BYTES 32768u          // 4 operand tiles x 8KB
#define NSTAGE 3

// bf16 split-2 operand storage (zero-initialized device globals)
__device__ __nv_bfloat16 g_xh[SQ * DIMN],  g_xl[SQ * DIMN];
__device__ __nv_bfloat16 g_wh[3 * DIMN * DIMN], g_wl[3 * DIMN * DIMN];
__device__ __nv_bfloat16 g_qh[SQ * DIMN],  g_ql[SQ * DIMN];
__device__ __nv_bfloat16 g_kh[SQ * DIMN],  g_kl[SQ * DIMN];  // pre-scaled by SCALE
__device__ __nv_bfloat16 g_vth[DIMN * SQ], g_vtl[DIMN * SQ];   // V^T: [512, 8192]
__device__ __nv_bfloat16 g_ah[(size_t)SQ * SQ], g_al[(size_t)SQ * SQ];  // attn split
// split-K partials for AV: 256 tiles x 8 segs x 128x128 fp32 = 128 MB
__device__ float g_part[(size_t)256 * 8 * 16384];

// ---------------------------------------------------------------------------
// PTX helpers (base-ISA only: ldmatrix / mma.sync / cp.async)
// ---------------------------------------------------------------------------
__device__ __forceinline__ uint32_t smem_u32(const void* p) {
    uint32_t a;
    asm("{ .reg .u64 t; cvta.to.shared.u64 t, %1; cvt.u32.u64 %0, t; }" : "=r"(a) : "l"(p));
    return a;
}
__device__ __forceinline__ void cp16(uint32_t dst, const void* src) {
    asm volatile("cp.async.cg.shared.global [%0], [%1], 16;" :: "r"(dst), "l"(src));
}
__device__ __forceinline__ void cp_commit() { asm volatile("cp.async.commit_group;" ::: "memory"); }
__device__ __forceinline__ void cp_wait1()  { asm volatile("cp.async.wait_group 1;" ::: "memory"); }
__device__ __forceinline__ void cp_wait0()  { asm volatile("cp.async.wait_group 0;" ::: "memory"); }
__device__ __forceinline__ void ldm_x4(uint32_t* r, uint32_t addr) {
    asm volatile("ldmatrix.sync.aligned.m8n8.x4.shared.b16 {%0,%1,%2,%3}, [%4];"
        : "=r"(r[0]), "=r"(r[1]), "=r"(r[2]), "=r"(r[3]) : "r"(addr));
}
__device__ __forceinline__ void mma_bf16(float* d, const uint32_t* a, const uint32_t* b) {
    asm volatile("mma.sync.aligned.m16n8k16.row.col.f32.bf16.bf16.f32 "
        "{%0,%1,%2,%3}, {%4,%5,%6,%7}, {%8,%9}, {%0,%1,%2,%3};"
        : "+f"(d[0]), "+f"(d[1]), "+f"(d[2]), "+f"(d[3])
        : "r"(a[0]), "r"(a[1]), "r"(a[2]), "r"(a[3]), "r"(b[0]), "r"(b[1]));
}
__device__ __forceinline__ void split2(float v, __nv_bfloat16& h, __nv_bfloat16& l) {
    h = __float2bfloat16(v);
    l = __float2bfloat16(v - __bfloat162float(h));
}

// Swizzled smem byte offset for (row, 16B-chunk) within a 128x32-bf16 tile (64B rows)
__device__ __forceinline__ uint32_t sw_off(int r, int c) {
    return (uint32_t)(r * 64 + ((c ^ ((r >> 1) & 3)) << 4));
}

// ---------------------------------------------------------------------------
// Issue one 32-wide K chunk (Ah,Al,Bh,Bl: 128 rows x 32 bf16 each) via cp.async
// ---------------------------------------------------------------------------
__device__ __forceinline__ void issue_chunk(
    uint32_t sb,
    const __nv_bfloat16* __restrict__ Ah, const __nv_bfloat16* __restrict__ Al, int sA,
    const __nv_bfloat16* __restrict__ Bh, const __nv_bfloat16* __restrict__ Bl, int sB,
    int tid)
{
    const int r  = tid >> 1;
    const int c0 = (tid & 1) * 2;
    const uint32_t o1 = sw_off(r, c0);
    const uint32_t o2 = sw_off(r, c0 + 1);
    const size_t ra = (size_t)r * sA + c0 * 8;
    const size_t rb = (size_t)r * sB + c0 * 8;
    cp16(sb +     0 + o1, Ah + ra);     cp16(sb +     0 + o2, Ah + ra + 8);
    cp16(sb +  8192 + o1, Al + ra);     cp16(sb +  8192 + o2, Al + ra + 8);
    cp16(sb + 16384 + o1, Bh + rb);     cp16(sb + 16384 + o2, Bh + rb + 8);
    cp16(sb + 24576 + o1, Bl + rb);     cp16(sb + 24576 + o2, Bl + rb + 8);
}

// ---------------------------------------------------------------------------
// Mainloop: acc[4][4][4] += 3-term split MMA over nchunks K-chunks.
// 3-stage cp.async pipeline, ONE __syncthreads per chunk (issue placed after
// the sync so stage (c+2)%3 writes can't race stage (c-1)%3 reads).
// CTA = 256 threads = 8 warps (2 x 4). Warp tile 64x32.
// ---------------------------------------------------------------------------
__device__ __forceinline__ void run_gemm(
    const __nv_bfloat16* __restrict__ Ah, const __nv_bfloat16* __restrict__ Al, int sA,
    const __nv_bfloat16* __restrict__ Bh, const __nv_bfloat16* __restrict__ Bl, int sB,
    int nchunks, uint32_t sbase, float acc[4][4][4])
{
    const int tid  = threadIdx.x;
    const int wid  = tid >> 5;
    const int lane = tid & 31;
    const int wm = (wid >> 2) * 64;   // warp row offset in CTA tile
    const int wn = (wid & 3) * 32;    // warp col offset
    const int lr = lane & 15;         // ldmatrix row-within-16
    const int lc = lane >> 4;         // ldmatrix k8-chunk select (0/1)

    issue_chunk(sbase, Ah, Al, sA, Bh, Bl, sB, tid);
    cp_commit();
    if (nchunks > 1)
        issue_chunk(sbase + STAGE_BYTES, Ah + KCHUNK, Al + KCHUNK, sA,
                    Bh + KCHUNK, Bl + KCHUNK, sB, tid);
    cp_commit();

    uint32_t st = sbase;
    int stage = 0;
    for (int c = 0; c < nchunks; c++) {
        if (c + 1 < nchunks) cp_wait1(); else cp_wait0();
        __syncthreads();
        if (c + 2 < nchunks) {
            const size_t ko = (size_t)(c + 2) * KCHUNK;
            int s2 = stage + 2; if (s2 >= NSTAGE) s2 -= NSTAGE;
            issue_chunk(sbase + (uint32_t)s2 * STAGE_BYTES,
                        Ah + ko, Al + ko, sA, Bh + ko, Bl + ko, sB, tid);
        }
        cp_commit();

        #pragma unroll
        for (int ks = 0; ks < 2; ks++) {
            const int kch = 2 * ks + lc;
            uint32_t aH[4][4], aL[4][4], bH[4][2], bL[4][2];
            #pragma unroll
            for (int i = 0; i < 4; i++) {
                int r = wm + i * 16 + lr;
                uint32_t off = sw_off(r, kch);
                ldm_x4(aH[i], st +    0 + off);
                ldm_x4(aL[i], st + 8192 + off);
            }
            #pragma unroll
            for (int j2 = 0; j2 < 2; j2++) {
                int r = wn + j2 * 16 + lr;
                uint32_t off = sw_off(r, kch);
                uint32_t t4[4];
                ldm_x4(t4, st + 16384 + off);
                bH[2*j2][0] = t4[0]; bH[2*j2+1][0] = t4[1];
                bH[2*j2][1] = t4[2]; bH[2*j2+1][1] = t4[3];
                ldm_x4(t4, st + 24576 + off);
                bL[2*j2][0] = t4[0]; bL[2*j2+1][0] = t4[1];
                bL[2*j2][1] = t4[2]; bL[2*j2+1][1] = t4[3];
            }
            #pragma unroll
            for (int i = 0; i < 4; i++)
                #pragma unroll
                for (int j = 0; j < 4; j++) {
                    mma_bf16(acc[i][j], aH[i], bH[j]);
                    mma_bf16(acc[i][j], aH[i], bL[j]);
                    mma_bf16(acc[i][j], aL[i], bH[j]);
                }
        }
        stage++; if (stage >= NSTAGE) stage = 0;
        st = sbase + (uint32_t)stage * STAGE_BYTES;
    }
}

// Accumulator element coords: tile (i,j), reg r ->
//   row = wm + i*16 + (lane>>2) + 8*(r>>1),  col = wn + j*8 + 2*(lane&3) + (r&1)

// ---------------------------------------------------------------------------
// Kernel: split x and W into bf16 hi/lo
// ---------------------------------------------------------------------------
__global__ __launch_bounds__(256) void conv_kernel(
    const float* __restrict__ x, const float* __restrict__ Wq,
    const float* __restrict__ Wk, const float* __restrict__ Wv)
{
    int idx = blockIdx.x * 256 + threadIdx.x;
    split2(x[idx], g_xh[idx], g_xl[idx]);
    if (idx < DIMN * DIMN) {
        split2(Wq[idx], g_wh[idx],                   g_wl[idx]);
        split2(Wk[idx], g_wh[DIMN * DIMN + idx],     g_wl[DIMN * DIMN + idx]);
        split2(Wv[idx], g_wh[2 * DIMN * DIMN + idx], g_wl[2 * DIMN * DIMN + idx]);
    }
}

// ---------------------------------------------------------------------------
// Kernel: QKV projection. grid (4, 64, 3). Emits q, k*SCALE, V^T (hi/lo each).
// ---------------------------------------------------------------------------
__global__ __launch_bounds__(256) void qkv_mma_kernel(
    const float* __restrict__ bq, const float* __restrict__ bk, const float* __restrict__ bv)
{
    extern __shared__ __align__(16) char dsm[];
    uint32_t sbase = smem_u32(dsm);

    const int z = blockIdx.z;
    const int row0 = blockIdx.y * 128;
    const int col0 = blockIdx.x * 128;
    const float* bias = (z == 0) ? bq : (z == 1) ? bk : bv;

    float acc[4][4][4];
    #pragma unroll
    for (int i = 0; i < 4; i++)
        #pragma unroll
        for (int j = 0; j < 4; j++)
            #pragma unroll
            for (int r = 0; r < 4; r++) acc[i][j][r] = 0.f;

    run_gemm(g_xh + (size_t)row0 * DIMN, g_xl + (size_t)row0 * DIMN, DIMN,
             g_wh + (size_t)z * DIMN * DIMN + (size_t)col0 * DIMN,
             g_wl + (size_t)z * DIMN * DIMN + (size_t)col0 * DIMN, DIMN,
             DIMN / KCHUNK, sbase, acc);

    const int tid = threadIdx.x, wid = tid >> 5, lane = tid & 31;
    const int wm = (wid >> 2) * 64, wn = (wid & 3) * 32;
    #pragma unroll
    for (int i = 0; i < 4; i++)
        #pragma unroll
        for (int j = 0; j < 4; j++)
            #pragma unroll
            for (int r = 0; r < 4; r++) {
                int rr = row0 + wm + i * 16 + (lane >> 2) + 8 * (r >> 1);
                int cc = col0 + wn + j * 8 + 2 * (lane & 3) + (r & 1);
                float v = acc[i][j][r] + bias[cc];
                if (z == 0)      split2(v, g_qh[(size_t)rr * DIMN + cc], g_ql[(size_t)rr * DIMN + cc]);
                else if (z == 1) split2(v * SCALE, g_kh[(size_t)rr * DIMN + cc], g_kl[(size_t)rr * DIMN + cc]);
                else             split2(v, g_vth[(size_t)cc * SQ + rr], g_vtl[(size_t)cc * SQ + rr]);
            }
}

// ---------------------------------------------------------------------------
// Kernel: raw causal scores (SCALE pre-folded into K). grid (64, 64).
// Upper-triangle tiles just zero-fill (those are the final weights) and exit.
// ---------------------------------------------------------------------------
__global__ __launch_bounds__(256) void scores_mma_kernel(float* __restrict__ attn)
{
    const int bi = blockIdx.y, bj = blockIdx.x;
    const int row0 = bi * 128, col0 = bj * 128;

    if (bj > bi) {
        float4 z = make_float4(0.f, 0.f, 0.f, 0.f);
        #pragma unroll 4
        for (int idx = threadIdx.x; idx < 128 * 32; idx += 256) {
            int r = idx >> 5, c = (idx & 31) << 2;
            *(float4*)(attn + (size_t)(row0 + r) * SQ + col0 + c) = z;
        }
        return;
    }

    extern __shared__ __align__(16) char dsm[];
    uint32_t sbase = smem_u32(dsm);

    float acc[4][4][4];
    #pragma unroll
    for (int i = 0; i < 4; i++)
        #pragma unroll
        for (int j = 0; j < 4; j++)
            #pragma unroll
            for (int r = 0; r < 4; r++) acc[i][j][r] = 0.f;

    run_gemm(g_qh + (size_t)row0 * DIMN, g_ql + (size_t)row0 * DIMN, DIMN,
             g_kh + (size_t)col0 * DIMN, g_kl + (size_t)col0 * DIMN, DIMN,
             DIMN / KCHUNK, sbase, acc);

    const int tid = threadIdx.x, wid = tid >> 5, lane = tid & 31;
    const int wm = (wid >> 2) * 64, wn = (wid & 3) * 32;
    const bool diag = (bi == bj);
    #pragma unroll
    for (int i = 0; i < 4; i++)
        #pragma unroll
        for (int j = 0; j < 4; j++)
            #pragma unroll
            for (int rh = 0; rh < 2; rh++) {
                int rr = row0 + wm + i * 16 + (lane >> 2) + 8 * rh;
                int cc = col0 + wn + j * 8 + 2 * (lane & 3);
                float2 v;
                v.x = acc[i][j][2 * rh + 0];
                v.y = acc[i][j][2 * rh + 1];
                if (diag) {
                    if (cc + 0 > rr) v.x = 0.f;
                    if (cc + 1 > rr) v.y = 0.f;
                }
                *(float2*)(attn + (size_t)rr * SQ + cc) = v;
            }
}

// ---------------------------------------------------------------------------
// Kernel: causal softmax in place + emit bf16 hi/lo weights for AV GEMM
// ---------------------------------------------------------------------------
__global__ __launch_bounds__(256) void softmax_kernel(float* __restrict__ attn)
{
    __shared__ float buf[SQ];
    __shared__ float red[32];
    __shared__ float s_bcast;

    const int i = blockIdx.x;
    const int L = i + 1;
    float* row = attn + (size_t)i * SQ;
    const int tid = threadIdx.x;

    float mx = -3.4e38f;
    for (int j = tid; j < L; j += 256) {
        float s = row[j];
        buf[j] = s;
        mx = fmaxf(mx, s);
    }
    #pragma unroll
    for (int o = 16; o; o >>= 1) mx = fmaxf(mx, __shfl_xor_sync(0xffffffffu, mx, o));
    if ((tid & 31) == 0) red[tid >> 5] = mx;
    __syncthreads();
    if (tid < 32) {
        float v = (tid < 8) ? red[tid] : -3.4e38f;
        #pragma unroll
        for (int o = 4; o; o >>= 1) v = fmaxf(v, __shfl_xor_sync(0xffffffffu, v, o));
        if (tid == 0) s_bcast = v;
    }
    __syncthreads();
    mx = s_bcast;

    float sum = 0.f;
    for (int j = tid; j < L; j += 256) {
        float e = __expf(buf[j] - mx);
        buf[j] = e;
        sum += e;
    }
    #pragma unroll
    for (int o = 16; o; o >>= 1) sum += __shfl_xor_sync(0xffffffffu, sum, o);
    __syncthreads();
    if ((tid & 31) == 0) red[tid >> 5] = sum;
    __syncthreads();
    if (tid < 32) {
        float v = (tid < 8) ? red[tid] : 0.f;
        #pragma unroll
        for (int o = 4; o; o >>= 1) v += __shfl_xor_sync(0xffffffffu, v, o);
        if (tid == 0) s_bcast = 1.f / v;
    }
    __syncthreads();
    const float inv = s_bcast;

    for (int j = tid; j < L; j += 256) {
        float w = buf[j] * inv;
        row[j] = w;
        __nv_bfloat16 h, l;
        split2(w, h, l);
        g_ah[(size_t)i * SQ + j] = h;
        g_al[(size_t)i * SQ + j] = l;
    }
}

// ---------------------------------------------------------------------------
// Kernel: output = attn @ V, uniform split-K units. grid (4, 64, 8):
//   bn = x, bm = y, seg = z; each unit covers K in [seg*1024, min(...)).
// nseg==1 tiles (bm<8) write out directly; otherwise fp32 partials to g_part.
// ---------------------------------------------------------------------------
__global__ __launch_bounds__(256) void av_mma_kernel(float* __restrict__ out)
{
    const int bn = blockIdx.x, bm = blockIdx.y, seg = blockIdx.z;
    const int nseg = (bm + 8) >> 3;            // ceil((bm+1)/8)
    if (seg >= nseg) return;

    const int row0 = bm * 128, col0 = bn * 128;
    const int k0 = seg * 1024;
    const int ktot = (bm + 1) * 128;
    const int kend = (k0 + 1024 < ktot) ? (k0 + 1024) : ktot;
    const int nchunks = (kend - k0) / KCHUNK;

    extern __shared__ __align__(16) char dsm[];
    uint32_t sbase = smem_u32(dsm);

    float acc[4][4][4];
    #pragma unroll
    for (int i = 0; i < 4; i++)
        #pragma unroll
        for (int j = 0; j < 4; j++)
            #pragma unroll
            for (int r = 0; r < 4; r++) acc[i][j][r] = 0.f;

    run_gemm(g_ah + (size_t)row0 * SQ + k0, g_al + (size_t)row0 * SQ + k0, SQ,
             g_vth + (size_t)col0 * SQ + k0, g_vtl + (size_t)col0 * SQ + k0, SQ,
             nchunks, sbase, acc);

    const int tid = threadIdx.x, wid = tid >> 5, lane = tid & 31;
    const int wm = (wid >> 2) * 64, wn = (wid & 3) * 32;

    if (nseg == 1) {
        #pragma unroll
        for (int i = 0; i < 4; i++)
            #pragma unroll
            for (int j = 0; j < 4; j++)
                #pragma unroll
                for (int rh = 0; rh < 2; rh++) {
                    int rr = row0 + wm + i * 16 + (lane >> 2) + 8 * rh;
                    int cc = col0 + wn + j * 8 + 2 * (lane & 3);
                    float2 v;
                    v.x = acc[i][j][2 * rh + 0];
                    v.y = acc[i][j][2 * rh + 1];
                    *(float2*)(out + (size_t)rr * DIMN + cc) = v;
                }
    } else {
        float* slot = g_part + ((size_t)((bm * 4 + bn) * 8 + seg)) * 16384;
        #pragma unroll
        for (int i = 0; i < 4; i++)
            #pragma unroll
            for (int j = 0; j < 4; j++)
                #pragma unroll
                for (int rh = 0; rh < 2; rh++) {
                    int lrr = wm + i * 16 + (lane >> 2) + 8 * rh;
                    int lcc = wn + j * 8 + 2 * (lane & 3);
                    float2 v;
                    v.x = acc[i][j][2 * rh + 0];
                    v.y = acc[i][j][2 * rh + 1];
                    *(float2*)(slot + lrr * 128 + lcc) = v;
                }
    }
}

// ---------------------------------------------------------------------------
// Kernel: deterministic split-K reduction for tiles with bm >= 8.
// grid (4, 56): bn = x, bm = 8 + y. Fixed seg order -> deterministic.
// ---------------------------------------------------------------------------
__global__ __launch_bounds__(256) void av_reduce_kernel(float* __restrict__ out)
{
    const int bn = blockIdx.x, bm = 8 + blockIdx.y;
    const int nseg = (bm + 8) >> 3;
    const int row0 = bm * 128, col0 = bn * 128;
    const float* base = g_part + ((size_t)((bm * 4 + bn) * 8)) * 16384;

    for (int idx = threadIdx.x; idx < 4096; idx += 256) {   // 4096 float4 = 16384 floats
        float4 s = *(const float4*)(base + idx * 4);
        for (int sg = 1; sg < nseg; sg++) {
            float4 p = *(const float4*)(base + (size_t)sg * 16384 + idx * 4);
            s.x += p.x; s.y += p.y; s.z += p.z; s.w += p.w;
        }
        int lr = idx >> 5, lc = (idx & 31) << 2;
        *(float4*)(out + (size_t)(row0 + lr) * DIMN + col0 + lc) = s;
    }
}

// ---------------------------------------------------------------------------
extern "C" void kernel_launch(void* const* d_in, const int* in_sizes, int n_in,
                              void* d_out, int out_size)
{
    const float* x  = (const float*)d_in[0];
    const float* Wq = (const float*)d_in[1];
    const float* bq = (const float*)d_in[2];
    const float* Wk = (const float*)d_in[3];
    const float* bk = (const float*)d_in[4];
    const float* Wv = (const float*)d_in[5];
    const float* bv = (const float*)d_in[6];

    float* out  = (float*)d_out;                 // [S, D]
    float* attn = out + (size_t)SQ * DIMN;       // [S, S]

    const int SMEM_BYTES = NSTAGE * (int)STAGE_BYTES;   // 96 KB -> 2 CTAs/SM
    cudaFuncSetAttribute(qkv_mma_kernel,    cudaFuncAttributeMaxDynamicSharedMemorySize, SMEM_BYTES);
    cudaFuncSetAttribute(scores_mma_kernel, cudaFuncAttributeMaxDynamicSharedMemorySize, SMEM_BYTES);
    cudaFuncSetAttribute(av_mma_kernel,     cudaFuncAttributeMaxDynamicSharedMemorySize, SMEM_BYTES);

    conv_kernel<<<(SQ * DIMN) / 256, 256>>>(x, Wq, Wk, Wv);

    dim3 g_qkv(DIMN / 128, SQ / 128, 3);
    qkv_mma_kernel<<<g_qkv, 256, SMEM_BYTES>>>(bq, bk, bv);

    dim3 g_sc(SQ / 128, SQ / 128);
    scores_mma_kernel<<<g_sc, 256, SMEM_BYTES>>>(attn);

    softmax_kernel<<<SQ, 256>>>(attn);

    dim3 g_av(4, 64, 8);
    av_mma_kernel<<<g_av, 256, SMEM_BYTES>>>(out);

    dim3 g_red(4, 56);
    av_reduce_kernel<<<g_red, 256>>>(out);
}

// round 5
// speedup vs baseline: 2.6667x; 1.0259x over previous
#include <cuda_runtime.h>
#include <cuda_bf16.h>
#include <cstdint>

#define SQ 8192
#define DIMN 512
#define SCALE 0.04419417382415922f  // 1/sqrt(512)
#define KCHUNK 32                   // k per pipeline stage (bf16)
#define STAGE_BYTES 32768u          // 4 operand tiles x 8KB
#define NSTAGE 3

// bf16 split-2 operand storage (zero-initialized device globals)
__device__ __nv_bfloat16 g_xh[SQ * DIMN],  g_xl[SQ * DIMN];
__device__ __nv_bfloat16 g_wh[3 * DIMN * DIMN], g_wl[3 * DIMN * DIMN];
__device__ __nv_bfloat16 g_qh[SQ * DIMN],  g_ql[SQ * DIMN];
__device__ __nv_bfloat16 g_kh[SQ * DIMN],  g_kl[SQ * DIMN];  // pre-scaled by SCALE
__device__ __nv_bfloat16 g_vth[DIMN * SQ], g_vtl[DIMN * SQ];   // V^T: [512, 8192]
__device__ __nv_bfloat16 g_ah[(size_t)SQ * SQ], g_al[(size_t)SQ * SQ];  // attn split
// split-K partials for AV: 256 tiles x 8 segs x 128x128 fp32
__device__ float g_part[(size_t)256 * 8 * 16384];

// ---------------------------------------------------------------------------
// PTX helpers (base-ISA only: ldmatrix / mma.sync / cp.async)
// ---------------------------------------------------------------------------
__device__ __forceinline__ uint32_t smem_u32(const void* p) {
    uint32_t a;
    asm("{ .reg .u64 t; cvta.to.shared.u64 t, %1; cvt.u32.u64 %0, t; }" : "=r"(a) : "l"(p));
    return a;
}
__device__ __forceinline__ void cp16(uint32_t dst, const void* src) {
    asm volatile("cp.async.cg.shared.global [%0], [%1], 16;" :: "r"(dst), "l"(src));
}
__device__ __forceinline__ void cp_commit() { asm volatile("cp.async.commit_group;" ::: "memory"); }
__device__ __forceinline__ void cp_wait1()  { asm volatile("cp.async.wait_group 1;" ::: "memory"); }
__device__ __forceinline__ void cp_wait0()  { asm volatile("cp.async.wait_group 0;" ::: "memory"); }
__device__ __forceinline__ void ldm_x4(uint32_t* r, uint32_t addr) {
    asm volatile("ldmatrix.sync.aligned.m8n8.x4.shared.b16 {%0,%1,%2,%3}, [%4];"
        : "=r"(r[0]), "=r"(r[1]), "=r"(r[2]), "=r"(r[3]) : "r"(addr));
}
__device__ __forceinline__ void mma_bf16(float* d, const uint32_t* a, const uint32_t* b) {
    asm volatile("mma.sync.aligned.m16n8k16.row.col.f32.bf16.bf16.f32 "
        "{%0,%1,%2,%3}, {%4,%5,%6,%7}, {%8,%9}, {%0,%1,%2,%3};"
        : "+f"(d[0]), "+f"(d[1]), "+f"(d[2]), "+f"(d[3])
        : "r"(a[0]), "r"(a[1]), "r"(a[2]), "r"(a[3]), "r"(b[0]), "r"(b[1]));
}
__device__ __forceinline__ void split2(float v, __nv_bfloat16& h, __nv_bfloat16& l) {
    h = __float2bfloat16(v);
    l = __float2bfloat16(v - __bfloat162float(h));
}
__device__ __forceinline__ uint32_t pack_bf2(__nv_bfloat16 a, __nv_bfloat16 b) {
    return (uint32_t)__bfloat16_as_ushort(a) | ((uint32_t)__bfloat16_as_ushort(b) << 16);
}

// Swizzled smem byte offset for (row, 16B-chunk) within a 128x32-bf16 tile (64B rows)
__device__ __forceinline__ uint32_t sw_off(int r, int c) {
    return (uint32_t)(r * 64 + ((c ^ ((r >> 1) & 3)) << 4));
}

// ---------------------------------------------------------------------------
// Issue one 32-wide K chunk (Ah,Al,Bh,Bl: 128 rows x 32 bf16 each) via cp.async
// ---------------------------------------------------------------------------
__device__ __forceinline__ void issue_chunk(
    uint32_t sb,
    const __nv_bfloat16* __restrict__ Ah, const __nv_bfloat16* __restrict__ Al, int sA,
    const __nv_bfloat16* __restrict__ Bh, const __nv_bfloat16* __restrict__ Bl, int sB,
    int tid)
{
    const int r  = tid >> 1;
    const int c0 = (tid & 1) * 2;
    const uint32_t o1 = sw_off(r, c0);
    const uint32_t o2 = sw_off(r, c0 + 1);
    const size_t ra = (size_t)r * sA + c0 * 8;
    const size_t rb = (size_t)r * sB + c0 * 8;
    cp16(sb +     0 + o1, Ah + ra);     cp16(sb +     0 + o2, Ah + ra + 8);
    cp16(sb +  8192 + o1, Al + ra);     cp16(sb +  8192 + o2, Al + ra + 8);
    cp16(sb + 16384 + o1, Bh + rb);     cp16(sb + 16384 + o2, Bh + rb + 8);
    cp16(sb + 24576 + o1, Bl + rb);     cp16(sb + 24576 + o2, Bl + rb + 8);
}

// ---------------------------------------------------------------------------
// Mainloop: acc[4][4][4] += 3-term split MMA over nchunks K-chunks.
// 3-stage cp.async pipeline, one __syncthreads per chunk.
// Inner order: B fragments first, then per-i {A ldsm -> 12 MMA} so HMMA
// issue starts early and next-i LDSMs overlap current MMAs.
// ---------------------------------------------------------------------------
__device__ __forceinline__ void run_gemm(
    const __nv_bfloat16* __restrict__ Ah, const __nv_bfloat16* __restrict__ Al, int sA,
    const __nv_bfloat16* __restrict__ Bh, const __nv_bfloat16* __restrict__ Bl, int sB,
    int nchunks, uint32_t sbase, float acc[4][4][4])
{
    const int tid  = threadIdx.x;
    const int wid  = tid >> 5;
    const int lane = tid & 31;
    const int wm = (wid >> 2) * 64;   // warp row offset in CTA tile
    const int wn = (wid & 3) * 32;    // warp col offset
    const int lr = lane & 15;         // ldmatrix row-within-16
    const int lc = lane >> 4;         // ldmatrix k8-chunk select (0/1)

    issue_chunk(sbase, Ah, Al, sA, Bh, Bl, sB, tid);
    cp_commit();
    if (nchunks > 1)
        issue_chunk(sbase + STAGE_BYTES, Ah + KCHUNK, Al + KCHUNK, sA,
                    Bh + KCHUNK, Bl + KCHUNK, sB, tid);
    cp_commit();

    uint32_t st = sbase;
    int stage = 0;
    for (int c = 0; c < nchunks; c++) {
        if (c + 1 < nchunks) cp_wait1(); else cp_wait0();
        __syncthreads();
        if (c + 2 < nchunks) {
            const size_t ko = (size_t)(c + 2) * KCHUNK;
            int s2 = stage + 2; if (s2 >= NSTAGE) s2 -= NSTAGE;
            issue_chunk(sbase + (uint32_t)s2 * STAGE_BYTES,
                        Ah + ko, Al + ko, sA, Bh + ko, Bl + ko, sB, tid);
        }
        cp_commit();

        #pragma unroll
        for (int ks = 0; ks < 2; ks++) {
            const int kch = 2 * ks + lc;
            uint32_t bH[4][2], bL[4][2];
            #pragma unroll
            for (int j2 = 0; j2 < 2; j2++) {
                int r = wn + j2 * 16 + lr;
                uint32_t off = sw_off(r, kch);
                uint32_t t4[4];
                ldm_x4(t4, st + 16384 + off);
                bH[2*j2][0] = t4[0]; bH[2*j2+1][0] = t4[1];
                bH[2*j2][1] = t4[2]; bH[2*j2+1][1] = t4[3];
                ldm_x4(t4, st + 24576 + off);
                bL[2*j2][0] = t4[0]; bL[2*j2+1][0] = t4[1];
                bL[2*j2][1] = t4[2]; bL[2*j2+1][1] = t4[3];
            }
            #pragma unroll
            for (int i = 0; i < 4; i++) {
                uint32_t aH[4], aL[4];
                int r = wm + i * 16 + lr;
                uint32_t off = sw_off(r, kch);
                ldm_x4(aH, st +    0 + off);
                ldm_x4(aL, st + 8192 + off);
                #pragma unroll
                for (int j = 0; j < 4; j++) {
                    mma_bf16(acc[i][j], aH, bH[j]);
                    mma_bf16(acc[i][j], aH, bL[j]);
                    mma_bf16(acc[i][j], aL, bH[j]);
                }
            }
        }
        stage++; if (stage >= NSTAGE) stage = 0;
        st = sbase + (uint32_t)stage * STAGE_BYTES;
    }
}

// Accumulator element coords: tile (i,j), reg r ->
//   row = wm + i*16 + (lane>>2) + 8*(r>>1),  col = wn + j*8 + 2*(lane&3) + (r&1)

// ---------------------------------------------------------------------------
// Kernel: split x and W into bf16 hi/lo
// ---------------------------------------------------------------------------
__global__ __launch_bounds__(256) void conv_kernel(
    const float* __restrict__ x, const float* __restrict__ Wq,
    const float* __restrict__ Wk, const float* __restrict__ Wv)
{
    int idx = blockIdx.x * 256 + threadIdx.x;
    split2(x[idx], g_xh[idx], g_xl[idx]);
    if (idx < DIMN * DIMN) {
        split2(Wq[idx], g_wh[idx],                   g_wl[idx]);
        split2(Wk[idx], g_wh[DIMN * DIMN + idx],     g_wl[DIMN * DIMN + idx]);
        split2(Wv[idx], g_wh[2 * DIMN * DIMN + idx], g_wl[2 * DIMN * DIMN + idx]);
    }
}

// ---------------------------------------------------------------------------
// Kernel: QKV projection. grid (4, 64, 3). Emits q, k*SCALE, V^T (hi/lo each).
// V^T goes through an smem transpose so the global stores are coalesced.
// ---------------------------------------------------------------------------
__global__ __launch_bounds__(256, 2) void qkv_mma_kernel(
    const float* __restrict__ bq, const float* __restrict__ bk, const float* __restrict__ bv)
{
    extern __shared__ __align__(16) char dsm[];
    uint32_t sbase = smem_u32(dsm);

    const int z = blockIdx.z;
    const int row0 = blockIdx.y * 128;
    const int col0 = blockIdx.x * 128;
    const float* bias = (z == 0) ? bq : (z == 1) ? bk : bv;

    float acc[4][4][4];
    #pragma unroll
    for (int i = 0; i < 4; i++)
        #pragma unroll
        for (int j = 0; j < 4; j++)
            #pragma unroll
            for (int r = 0; r < 4; r++) acc[i][j][r] = 0.f;

    run_gemm(g_xh + (size_t)row0 * DIMN, g_xl + (size_t)row0 * DIMN, DIMN,
             g_wh + (size_t)z * DIMN * DIMN + (size_t)col0 * DIMN,
             g_wl + (size_t)z * DIMN * DIMN + (size_t)col0 * DIMN, DIMN,
             DIMN / KCHUNK, sbase, acc);

    const int tid = threadIdx.x, wid = tid >> 5, lane = tid & 31;
    const int wm = (wid >> 2) * 64, wn = (wid & 3) * 32;

    if (z < 2) {
        #pragma unroll
        for (int i = 0; i < 4; i++)
            #pragma unroll
            for (int j = 0; j < 4; j++)
                #pragma unroll
                for (int r = 0; r < 4; r++) {
                    int rr = row0 + wm + i * 16 + (lane >> 2) + 8 * (r >> 1);
                    int cc = col0 + wn + j * 8 + 2 * (lane & 3) + (r & 1);
                    float v = acc[i][j][r] + bias[cc];
                    if (z == 0) split2(v, g_qh[(size_t)rr * DIMN + cc], g_ql[(size_t)rr * DIMN + cc]);
                    else        split2(v * SCALE, g_kh[(size_t)rr * DIMN + cc], g_kl[(size_t)rr * DIMN + cc]);
                }
    } else {
        // V: transpose through smem, then coalesced packed stores to g_vth/g_vtl
        __syncthreads();                       // pipeline smem no longer in use
        float* tsm = (float*)dsm;              // [128][132] transposed tile
        #pragma unroll
        for (int i = 0; i < 4; i++)
            #pragma unroll
            for (int j = 0; j < 4; j++)
                #pragma unroll
                for (int r = 0; r < 4; r++) {
                    int lrr = wm + i * 16 + (lane >> 2) + 8 * (r >> 1);
                    int lcc = wn + j * 8 + 2 * (lane & 3) + (r & 1);
                    tsm[lcc * 132 + lrr] = acc[i][j][r] + bias[col0 + lcc];
                }
        __syncthreads();
        #pragma unroll
        for (int it = 0; it < 8; it++) {
            int idx = it * 256 + tid;          // 0..2047
            int vr = idx >> 4;                 // local headdim row 0..127
            int c8 = (idx & 15) * 8;           // 8-wide chunk along seq
            uint32_t hw[4], lw[4];
            #pragma unroll
            for (int m = 0; m < 4; m++) {
                float v0 = tsm[vr * 132 + c8 + 2 * m];
                float v1 = tsm[vr * 132 + c8 + 2 * m + 1];
                __nv_bfloat16 h0, l0, h1, l1;
                split2(v0, h0, l0);
                split2(v1, h1, l1);
                hw[m] = pack_bf2(h0, h1);
                lw[m] = pack_bf2(l0, l1);
            }
            size_t base = (size_t)(col0 + vr) * SQ + row0 + c8;
            *(uint4*)(g_vth + base) = make_uint4(hw[0], hw[1], hw[2], hw[3]);
            *(uint4*)(g_vtl + base) = make_uint4(lw[0], lw[1], lw[2], lw[3]);
        }
    }
}

// ---------------------------------------------------------------------------
// Kernel: raw causal scores (SCALE pre-folded into K). grid (64, 64).
// Upper-triangle tiles just zero-fill (those are the final weights) and exit.
// ---------------------------------------------------------------------------
__global__ __launch_bounds__(256, 2) void scores_mma_kernel(float* __restrict__ attn)
{
    const int bi = blockIdx.y, bj = blockIdx.x;
    const int row0 = bi * 128, col0 = bj * 128;

    if (bj > bi) {
        float4 z = make_float4(0.f, 0.f, 0.f, 0.f);
        #pragma unroll 4
        for (int idx = threadIdx.x; idx < 128 * 32; idx += 256) {
            int r = idx >> 5, c = (idx & 31) << 2;
            *(float4*)(attn + (size_t)(row0 + r) * SQ + col0 + c) = z;
        }
        return;
    }

    extern __shared__ __align__(16) char dsm[];
    uint32_t sbase = smem_u32(dsm);

    float acc[4][4][4];
    #pragma unroll
    for (int i = 0; i < 4; i++)
        #pragma unroll
        for (int j = 0; j < 4; j++)
            #pragma unroll
            for (int r = 0; r < 4; r++) acc[i][j][r] = 0.f;

    run_gemm(g_qh + (size_t)row0 * DIMN, g_ql + (size_t)row0 * DIMN, DIMN,
             g_kh + (size_t)col0 * DIMN, g_kl + (size_t)col0 * DIMN, DIMN,
             DIMN / KCHUNK, sbase, acc);

    const int tid = threadIdx.x, wid = tid >> 5, lane = tid & 31;
    const int wm = (wid >> 2) * 64, wn = (wid & 3) * 32;
    const bool diag = (bi == bj);
    #pragma unroll
    for (int i = 0; i < 4; i++)
        #pragma unroll
        for (int j = 0; j < 4; j++)
            #pragma unroll
            for (int rh = 0; rh < 2; rh++) {
                int rr = row0 + wm + i * 16 + (lane >> 2) + 8 * rh;
                int cc = col0 + wn + j * 8 + 2 * (lane & 3);
                float2 v;
                v.x = acc[i][j][2 * rh + 0];
                v.y = acc[i][j][2 * rh + 1];
                if (diag) {
                    if (cc + 0 > rr) v.x = 0.f;
                    if (cc + 1 > rr) v.y = 0.f;
                }
                *(float2*)(attn + (size_t)rr * SQ + cc) = v;
            }
}

// ---------------------------------------------------------------------------
// Kernel: causal softmax in place + emit bf16 hi/lo weights. Vectorized.
// ---------------------------------------------------------------------------
__global__ __launch_bounds__(256) void softmax_kernel(float* __restrict__ attn)
{
    __shared__ __align__(16) float buf[SQ];
    __shared__ float red[32];
    __shared__ float s_bcast;

    const int i = blockIdx.x;
    const int L = i + 1;
    const int L4 = L >> 2;
    const int tail = L & 3;
    float* row = attn + (size_t)i * SQ;
    const int tid = threadIdx.x;

    float mx = -3.4e38f;
    for (int j4 = tid; j4 < L4; j4 += 256) {
        float4 s = ((const float4*)row)[j4];
        ((float4*)buf)[j4] = s;
        mx = fmaxf(fmaxf(mx, fmaxf(s.x, s.y)), fmaxf(s.z, s.w));
    }
    if (tid < tail) {
        int j = L4 * 4 + tid;
        float s = row[j];
        buf[j] = s;
        mx = fmaxf(mx, s);
    }
    #pragma unroll
    for (int o = 16; o; o >>= 1) mx = fmaxf(mx, __shfl_xor_sync(0xffffffffu, mx, o));
    if ((tid & 31) == 0) red[tid >> 5] = mx;
    __syncthreads();
    if (tid < 32) {
        float v = (tid < 8) ? red[tid] : -3.4e38f;
        #pragma unroll
        for (int o = 4; o; o >>= 1) v = fmaxf(v, __shfl_xor_sync(0xffffffffu, v, o));
        if (tid == 0) s_bcast = v;
    }
    __syncthreads();
    mx = s_bcast;

    float sum = 0.f;
    for (int j4 = tid; j4 < L4; j4 += 256) {
        float4 e = ((const float4*)buf)[j4];
        e.x = __expf(e.x - mx); e.y = __expf(e.y - mx);
        e.z = __expf(e.z - mx); e.w = __expf(e.w - mx);
        ((float4*)buf)[j4] = e;
        sum += (e.x + e.y) + (e.z + e.w);
    }
    if (tid < tail) {
        int j = L4 * 4 + tid;
        float e = __expf(buf[j] - mx);
        buf[j] = e;
        sum += e;
    }
    #pragma unroll
    for (int o = 16; o; o >>= 1) sum += __shfl_xor_sync(0xffffffffu, sum, o);
    __syncthreads();
    if ((tid & 31) == 0) red[tid >> 5] = sum;
    __syncthreads();
    if (tid < 32) {
        float v = (tid < 8) ? red[tid] : 0.f;
        #pragma unroll
        for (int o = 4; o; o >>= 1) v += __shfl_xor_sync(0xffffffffu, v, o);
        if (tid == 0) s_bcast = 1.f / v;
    }
    __syncthreads();
    const float inv = s_bcast;

    __nv_bfloat16* ah = g_ah + (size_t)i * SQ;
    __nv_bfloat16* al = g_al + (size_t)i * SQ;
    for (int j4 = tid; j4 < L4; j4 += 256) {
        float4 w = ((const float4*)buf)[j4];
        w.x *= inv; w.y *= inv; w.z *= inv; w.w *= inv;
        ((float4*)row)[j4] = w;
        __nv_bfloat16 h0, l0, h1, l1, h2, l2, h3, l3;
        split2(w.x, h0, l0); split2(w.y, h1, l1);
        split2(w.z, h2, l2); split2(w.w, h3, l3);
        uint2 hw, lw;
        hw.x = pack_bf2(h0, h1); hw.y = pack_bf2(h2, h3);
        lw.x = pack_bf2(l0, l1); lw.y = pack_bf2(l2, l3);
        *(uint2*)(ah + j4 * 4) = hw;
        *(uint2*)(al + j4 * 4) = lw;
    }
    if (tid < tail) {
        int j = L4 * 4 + tid;
        float w = buf[j] * inv;
        row[j] = w;
        __nv_bfloat16 h, l;
        split2(w, h, l);
        ah[j] = h;
        al[j] = l;
    }
}

// ---------------------------------------------------------------------------
// Kernel: output = attn @ V, uniform split-K units. grid (4, 64, 8).
// ---------------------------------------------------------------------------
__global__ __launch_bounds__(256, 2) void av_mma_kernel(float* __restrict__ out)
{
    const int bn = blockIdx.x, bm = blockIdx.y, seg = blockIdx.z;
    const int nseg = (bm + 8) >> 3;            // ceil((bm+1)/8)
    if (seg >= nseg) return;

    const int row0 = bm * 128, col0 = bn * 128;
    const int k0 = seg * 1024;
    const int ktot = (bm + 1) * 128;
    const int kend = (k0 + 1024 < ktot) ? (k0 + 1024) : ktot;
    const int nchunks = (kend - k0) / KCHUNK;

    extern __shared__ __align__(16) char dsm[];
    uint32_t sbase = smem_u32(dsm);

    float acc[4][4][4];
    #pragma unroll
    for (int i = 0; i < 4; i++)
        #pragma unroll
        for (int j = 0; j < 4; j++)
            #pragma unroll
            for (int r = 0; r < 4; r++) acc[i][j][r] = 0.f;

    run_gemm(g_ah + (size_t)row0 * SQ + k0, g_al + (size_t)row0 * SQ + k0, SQ,
             g_vth + (size_t)col0 * SQ + k0, g_vtl + (size_t)col0 * SQ + k0, SQ,
             nchunks, sbase, acc);

    const int tid = threadIdx.x, wid = tid >> 5, lane = tid & 31;
    const int wm = (wid >> 2) * 64, wn = (wid & 3) * 32;

    if (nseg == 1) {
        #pragma unroll
        for (int i = 0; i < 4; i++)
            #pragma unroll
            for (int j = 0; j < 4; j++)
                #pragma unroll
                for (int rh = 0; rh < 2; rh++) {
                    int rr = row0 + wm + i * 16 + (lane >> 2) + 8 * rh;
                    int cc = col0 + wn + j * 8 + 2 * (lane & 3);
                    float2 v;
                    v.x = acc[i][j][2 * rh + 0];
                    v.y = acc[i][j][2 * rh + 1];
                    *(float2*)(out + (size_t)rr * DIMN + cc) = v;
                }
    } else {
        float* slot = g_part + ((size_t)((bm * 4 + bn) * 8 + seg)) * 16384;
        #pragma unroll
        for (int i = 0; i < 4; i++)
            #pragma unroll
            for (int j = 0; j < 4; j++)
                #pragma unroll
                for (int rh = 0; rh < 2; rh++) {
                    int lrr = wm + i * 16 + (lane >> 2) + 8 * rh;
                    int lcc = wn + j * 8 + 2 * (lane & 3);
                    float2 v;
                    v.x = acc[i][j][2 * rh + 0];
                    v.y = acc[i][j][2 * rh + 1];
                    *(float2*)(slot + lrr * 128 + lcc) = v;
                }
    }
}

// ---------------------------------------------------------------------------
// Kernel: deterministic split-K reduction for tiles with bm >= 8.
// ---------------------------------------------------------------------------
__global__ __launch_bounds__(256) void av_reduce_kernel(float* __restrict__ out)
{
    const int bn = blockIdx.x, bm = 8 + blockIdx.y;
    const int nseg = (bm + 8) >> 3;
    const int row0 = bm * 128, col0 = bn * 128;
    const float* base = g_part + ((size_t)((bm * 4 + bn) * 8)) * 16384;

    for (int idx = threadIdx.x; idx < 4096; idx += 256) {
        float4 s = *(const float4*)(base + idx * 4);
        for (int sg = 1; sg < nseg; sg++) {
            float4 p = *(const float4*)(base + (size_t)sg * 16384 + idx * 4);
            s.x += p.x; s.y += p.y; s.z += p.z; s.w += p.w;
        }
        int lr = idx >> 5, lc = (idx & 31) << 2;
        *(float4*)(out + (size_t)(row0 + lr) * DIMN + col0 + lc) = s;
    }
}

// ---------------------------------------------------------------------------
extern "C" void kernel_launch(void* const* d_in, const int* in_sizes, int n_in,
                              void* d_out, int out_size)
{
    const float* x  = (const float*)d_in[0];
    const float* Wq = (const float*)d_in[1];
    const float* bq = (const float*)d_in[2];
    const float* Wk = (const float*)d_in[3];
    const float* bk = (const float*)d_in[4];
    const float* Wv = (const float*)d_in[5];
    const float* bv = (const float*)d_in[6];

    float* out  = (float*)d_out;                 // [S, D]
    float* attn = out + (size_t)SQ * DIMN;       // [S, S]

    const int SMEM_BYTES = NSTAGE * (int)STAGE_BYTES;   // 96 KB -> 2 CTAs/SM
    cudaFuncSetAttribute(qkv_mma_kernel,    cudaFuncAttributeMaxDynamicSharedMemorySize, SMEM_BYTES);
    cudaFuncSetAttribute(scores_mma_kernel, cudaFuncAttributeMaxDynamicSharedMemorySize, SMEM_BYTES);
    cudaFuncSetAttribute(av_mma_kernel,     cudaFuncAttributeMaxDynamicSharedMemorySize, SMEM_BYTES);

    conv_kernel<<<(SQ * DIMN) / 256, 256>>>(x, Wq, Wk, Wv);

    dim3 g_qkv(DIMN / 128, SQ / 128, 3);
    qkv_mma_kernel<<<g_qkv, 256, SMEM_BYTES>>>(bq, bk, bv);

    dim3 g_sc(SQ / 128, SQ / 128);
    scores_mma_kernel<<<g_sc, 256, SMEM_BYTES>>>(attn);

    softmax_kernel<<<SQ, 256>>>(attn);

    dim3 g_av(4, 64, 8);
    av_mma_kernel<<<g_av, 256, SMEM_BYTES>>>(out);

    dim3 g_red(4, 56);
    av_reduce_kernel<<<g_red, 256>>>(out);
}

// round 6
// speedup vs baseline: 3.0603x; 1.1476x over previous
#include <cuda_runtime.h>
#include <cuda_bf16.h>
#include <cuda_fp16.h>
#include <cstdint>

#define SQ 8192
#define DIMN 512
#define SCALE 0.04419417382415922f  // 1/sqrt(512)
#define KCHUNK 32                   // k per pipeline stage
#define STAGE_BYTES 32768u          // scores/qkv: 4 operand tiles x 8KB
#define NSTAGE 3
#define AV_STAGE_BYTES 24576u       // av: W 8KB + Vh 8KB + Vl 8KB
#define AV_NSTAGE 4

// bf16 split-2 operands for QKV/scores (zero-initialized device globals)
__device__ __nv_bfloat16 g_xh[SQ * DIMN],  g_xl[SQ * DIMN];
__device__ __nv_bfloat16 g_wh[3 * DIMN * DIMN], g_wl[3 * DIMN * DIMN];
__device__ __nv_bfloat16 g_qh[SQ * DIMN],  g_ql[SQ * DIMN];
__device__ __nv_bfloat16 g_kh[SQ * DIMN],  g_kl[SQ * DIMN];  // pre-scaled by SCALE
// fp16 operands for AV: V^T split-2, attn weights single (nonneg -> no cancellation)
__device__ __half g_vth[DIMN * SQ], g_vtl[DIMN * SQ];          // V^T: [512, 8192]
__device__ __half g_aw[(size_t)SQ * SQ];                       // weights fp16 (zero-init)
// split-K partials for AV
__device__ float g_part[(size_t)256 * 8 * 16384];

// ---------------------------------------------------------------------------
// PTX helpers (base-ISA only: ldmatrix / mma.sync / cp.async)
// ---------------------------------------------------------------------------
__device__ __forceinline__ uint32_t smem_u32(const void* p) {
    uint32_t a;
    asm("{ .reg .u64 t; cvta.to.shared.u64 t, %1; cvt.u32.u64 %0, t; }" : "=r"(a) : "l"(p));
    return a;
}
__device__ __forceinline__ void cp16(uint32_t dst, const void* src) {
    asm volatile("cp.async.cg.shared.global [%0], [%1], 16;" :: "r"(dst), "l"(src));
}
__device__ __forceinline__ void cp_commit() { asm volatile("cp.async.commit_group;" ::: "memory"); }
__device__ __forceinline__ void cp_wait0()  { asm volatile("cp.async.wait_group 0;" ::: "memory"); }
__device__ __forceinline__ void cp_wait1()  { asm volatile("cp.async.wait_group 1;" ::: "memory"); }
__device__ __forceinline__ void cp_wait2()  { asm volatile("cp.async.wait_group 2;" ::: "memory"); }
__device__ __forceinline__ void ldm_x4(uint32_t* r, uint32_t addr) {
    asm volatile("ldmatrix.sync.aligned.m8n8.x4.shared.b16 {%0,%1,%2,%3}, [%4];"
        : "=r"(r[0]), "=r"(r[1]), "=r"(r[2]), "=r"(r[3]) : "r"(addr));
}
__device__ __forceinline__ void mma_bf16(float* d, const uint32_t* a, const uint32_t* b) {
    asm volatile("mma.sync.aligned.m16n8k16.row.col.f32.bf16.bf16.f32 "
        "{%0,%1,%2,%3}, {%4,%5,%6,%7}, {%8,%9}, {%0,%1,%2,%3};"
        : "+f"(d[0]), "+f"(d[1]), "+f"(d[2]), "+f"(d[3])
        : "r"(a[0]), "r"(a[1]), "r"(a[2]), "r"(a[3]), "r"(b[0]), "r"(b[1]));
}
__device__ __forceinline__ void mma_f16(float* d, const uint32_t* a, const uint32_t* b) {
    asm volatile("mma.sync.aligned.m16n8k16.row.col.f32.f16.f16.f32 "
        "{%0,%1,%2,%3}, {%4,%5,%6,%7}, {%8,%9}, {%0,%1,%2,%3};"
        : "+f"(d[0]), "+f"(d[1]), "+f"(d[2]), "+f"(d[3])
        : "r"(a[0]), "r"(a[1]), "r"(a[2]), "r"(a[3]), "r"(b[0]), "r"(b[1]));
}
__device__ __forceinline__ void split2(float v, __nv_bfloat16& h, __nv_bfloat16& l) {
    h = __float2bfloat16(v);
    l = __float2bfloat16(v - __bfloat162float(h));
}
__device__ __forceinline__ void split2h(float v, __half& h, __half& l) {
    h = __float2half_rn(v);
    l = __float2half_rn(v - __half2float(h));
}
__device__ __forceinline__ uint32_t pack_bf2(__nv_bfloat16 a, __nv_bfloat16 b) {
    return (uint32_t)__bfloat16_as_ushort(a) | ((uint32_t)__bfloat16_as_ushort(b) << 16);
}
__device__ __forceinline__ uint32_t pack_h2(__half a, __half b) {
    return (uint32_t)__half_as_ushort(a) | ((uint32_t)__half_as_ushort(b) << 16);
}

// Swizzled smem byte offset for (row, 16B-chunk) within a 128x32x16bit tile (64B rows)
__device__ __forceinline__ uint32_t sw_off(int r, int c) {
    return (uint32_t)(r * 64 + ((c ^ ((r >> 1) & 3)) << 4));
}

// ---------------------------------------------------------------------------
// Chunk loaders
// ---------------------------------------------------------------------------
__device__ __forceinline__ void issue_chunk(
    uint32_t sb,
    const __nv_bfloat16* __restrict__ Ah, const __nv_bfloat16* __restrict__ Al, int sA,
    const __nv_bfloat16* __restrict__ Bh, const __nv_bfloat16* __restrict__ Bl, int sB,
    int tid)
{
    const int r  = tid >> 1;
    const int c0 = (tid & 1) * 2;
    const uint32_t o1 = sw_off(r, c0);
    const uint32_t o2 = sw_off(r, c0 + 1);
    const size_t ra = (size_t)r * sA + c0 * 8;
    const size_t rb = (size_t)r * sB + c0 * 8;
    cp16(sb +     0 + o1, Ah + ra);     cp16(sb +     0 + o2, Ah + ra + 8);
    cp16(sb +  8192 + o1, Al + ra);     cp16(sb +  8192 + o2, Al + ra + 8);
    cp16(sb + 16384 + o1, Bh + rb);     cp16(sb + 16384 + o2, Bh + rb + 8);
    cp16(sb + 24576 + o1, Bl + rb);     cp16(sb + 24576 + o2, Bl + rb + 8);
}

__device__ __forceinline__ void issue_chunk_av(
    uint32_t sb,
    const __half* __restrict__ W, int sA,
    const __half* __restrict__ Vh, const __half* __restrict__ Vl, int sB,
    int tid)
{
    const int r  = tid >> 1;
    const int c0 = (tid & 1) * 2;
    const uint32_t o1 = sw_off(r, c0);
    const uint32_t o2 = sw_off(r, c0 + 1);
    const size_t ra = (size_t)r * sA + c0 * 8;
    const size_t rb = (size_t)r * sB + c0 * 8;
    cp16(sb +     0 + o1, W  + ra);     cp16(sb +     0 + o2, W  + ra + 8);
    cp16(sb +  8192 + o1, Vh + rb);     cp16(sb +  8192 + o2, Vh + rb + 8);
    cp16(sb + 16384 + o1, Vl + rb);     cp16(sb + 16384 + o2, Vl + rb + 8);
}

// ---------------------------------------------------------------------------
// bf16 3-term mainloop (QKV, scores). 3-stage pipeline, one sync per chunk.
// ---------------------------------------------------------------------------
__device__ __forceinline__ void run_gemm(
    const __nv_bfloat16* __restrict__ Ah, const __nv_bfloat16* __restrict__ Al, int sA,
    const __nv_bfloat16* __restrict__ Bh, const __nv_bfloat16* __restrict__ Bl, int sB,
    int nchunks, uint32_t sbase, float acc[4][4][4])
{
    const int tid  = threadIdx.x;
    const int wid  = tid >> 5;
    const int lane = tid & 31;
    const int wm = (wid >> 2) * 64;
    const int wn = (wid & 3) * 32;
    const int lr = lane & 15;
    const int lc = lane >> 4;

    issue_chunk(sbase, Ah, Al, sA, Bh, Bl, sB, tid);
    cp_commit();
    if (nchunks > 1)
        issue_chunk(sbase + STAGE_BYTES, Ah + KCHUNK, Al + KCHUNK, sA,
                    Bh + KCHUNK, Bl + KCHUNK, sB, tid);
    cp_commit();

    uint32_t st = sbase;
    int stage = 0;
    for (int c = 0; c < nchunks; c++) {
        if (c + 1 < nchunks) cp_wait1(); else cp_wait0();
        __syncthreads();
        if (c + 2 < nchunks) {
            const size_t ko = (size_t)(c + 2) * KCHUNK;
            int s2 = stage + 2; if (s2 >= NSTAGE) s2 -= NSTAGE;
            issue_chunk(sbase + (uint32_t)s2 * STAGE_BYTES,
                        Ah + ko, Al + ko, sA, Bh + ko, Bl + ko, sB, tid);
        }
        cp_commit();

        #pragma unroll
        for (int ks = 0; ks < 2; ks++) {
            const int kch = 2 * ks + lc;
            uint32_t bH[4][2], bL[4][2];
            #pragma unroll
            for (int j2 = 0; j2 < 2; j2++) {
                int r = wn + j2 * 16 + lr;
                uint32_t off = sw_off(r, kch);
                uint32_t t4[4];
                ldm_x4(t4, st + 16384 + off);
                bH[2*j2][0] = t4[0]; bH[2*j2+1][0] = t4[1];
                bH[2*j2][1] = t4[2]; bH[2*j2+1][1] = t4[3];
                ldm_x4(t4, st + 24576 + off);
                bL[2*j2][0] = t4[0]; bL[2*j2+1][0] = t4[1];
                bL[2*j2][1] = t4[2]; bL[2*j2+1][1] = t4[3];
            }
            #pragma unroll
            for (int i = 0; i < 4; i++) {
                uint32_t aH[4], aL[4];
                int r = wm + i * 16 + lr;
                uint32_t off = sw_off(r, kch);
                ldm_x4(aH, st +    0 + off);
                ldm_x4(aL, st + 8192 + off);
                #pragma unroll
                for (int j = 0; j < 4; j++) {
                    mma_bf16(acc[i][j], aH, bH[j]);
                    mma_bf16(acc[i][j], aH, bL[j]);
                    mma_bf16(acc[i][j], aL, bH[j]);
                }
            }
        }
        stage++; if (stage >= NSTAGE) stage = 0;
        st = sbase + (uint32_t)stage * STAGE_BYTES;
    }
}

// ---------------------------------------------------------------------------
// fp16 2-term mainloop (AV): out += W(fp16) * (Vh + Vl). 4-stage pipeline.
// ---------------------------------------------------------------------------
__device__ __forceinline__ void run_gemm_av(
    const __half* __restrict__ W, int sA,
    const __half* __restrict__ Vh, const __half* __restrict__ Vl, int sB,
    int nchunks, uint32_t sbase, float acc[4][4][4])
{
    const int tid  = threadIdx.x;
    const int wid  = tid >> 5;
    const int lane = tid & 31;
    const int wm = (wid >> 2) * 64;
    const int wn = (wid & 3) * 32;
    const int lr = lane & 15;
    const int lc = lane >> 4;

    #pragma unroll
    for (int p = 0; p < 3; p++) {
        if (p < nchunks)
            issue_chunk_av(sbase + (uint32_t)p * AV_STAGE_BYTES,
                           W + (size_t)p * KCHUNK, sA,
                           Vh + (size_t)p * KCHUNK, Vl + (size_t)p * KCHUNK, sB, tid);
        cp_commit();
    }

    uint32_t st = sbase;
    int stage = 0;
    for (int c = 0; c < nchunks; c++) {
        cp_wait2();
        __syncthreads();
        if (c + 3 < nchunks) {
            const size_t ko = (size_t)(c + 3) * KCHUNK;
            int s3 = stage + 3; if (s3 >= AV_NSTAGE) s3 -= AV_NSTAGE;
            issue_chunk_av(sbase + (uint32_t)s3 * AV_STAGE_BYTES,
                           W + ko, sA, Vh + ko, Vl + ko, sB, tid);
        }
        cp_commit();

        #pragma unroll
        for (int ks = 0; ks < 2; ks++) {
            const int kch = 2 * ks + lc;
            uint32_t bH[4][2], bL[4][2];
            #pragma unroll
            for (int j2 = 0; j2 < 2; j2++) {
                int r = wn + j2 * 16 + lr;
                uint32_t off = sw_off(r, kch);
                uint32_t t4[4];
                ldm_x4(t4, st +  8192 + off);
                bH[2*j2][0] = t4[0]; bH[2*j2+1][0] = t4[1];
                bH[2*j2][1] = t4[2]; bH[2*j2+1][1] = t4[3];
                ldm_x4(t4, st + 16384 + off);
                bL[2*j2][0] = t4[0]; bL[2*j2+1][0] = t4[1];
                bL[2*j2][1] = t4[2]; bL[2*j2+1][1] = t4[3];
            }
            #pragma unroll
            for (int i = 0; i < 4; i++) {
                uint32_t aW[4];
                int r = wm + i * 16 + lr;
                ldm_x4(aW, st + sw_off(r, kch));
                #pragma unroll
                for (int j = 0; j < 4; j++) {
                    mma_f16(acc[i][j], aW, bH[j]);
                    mma_f16(acc[i][j], aW, bL[j]);
                }
            }
        }
        stage++; if (stage >= AV_NSTAGE) stage = 0;
        st = sbase + (uint32_t)stage * AV_STAGE_BYTES;
    }
}

// Accumulator element coords: tile (i,j), reg r ->
//   row = wm + i*16 + (lane>>2) + 8*(r>>1),  col = wn + j*8 + 2*(lane&3) + (r&1)

// ---------------------------------------------------------------------------
__global__ __launch_bounds__(256) void conv_kernel(
    const float* __restrict__ x, const float* __restrict__ Wq,
    const float* __restrict__ Wk, const float* __restrict__ Wv)
{
    int idx = blockIdx.x * 256 + threadIdx.x;
    split2(x[idx], g_xh[idx], g_xl[idx]);
    if (idx < DIMN * DIMN) {
        split2(Wq[idx], g_wh[idx],                   g_wl[idx]);
        split2(Wk[idx], g_wh[DIMN * DIMN + idx],     g_wl[DIMN * DIMN + idx]);
        split2(Wv[idx], g_wh[2 * DIMN * DIMN + idx], g_wl[2 * DIMN * DIMN + idx]);
    }
}

// ---------------------------------------------------------------------------
// QKV projection. grid (4, 64, 3). Emits q, k*SCALE (bf16 hi/lo), V^T (fp16 hi/lo).
// ---------------------------------------------------------------------------
__global__ __launch_bounds__(256, 2) void qkv_mma_kernel(
    const float* __restrict__ bq, const float* __restrict__ bk, const float* __restrict__ bv)
{
    extern __shared__ __align__(16) char dsm[];
    uint32_t sbase = smem_u32(dsm);

    const int z = blockIdx.z;
    const int row0 = blockIdx.y * 128;
    const int col0 = blockIdx.x * 128;
    const float* bias = (z == 0) ? bq : (z == 1) ? bk : bv;

    float acc[4][4][4];
    #pragma unroll
    for (int i = 0; i < 4; i++)
        #pragma unroll
        for (int j = 0; j < 4; j++)
            #pragma unroll
            for (int r = 0; r < 4; r++) acc[i][j][r] = 0.f;

    run_gemm(g_xh + (size_t)row0 * DIMN, g_xl + (size_t)row0 * DIMN, DIMN,
             g_wh + (size_t)z * DIMN * DIMN + (size_t)col0 * DIMN,
             g_wl + (size_t)z * DIMN * DIMN + (size_t)col0 * DIMN, DIMN,
             DIMN / KCHUNK, sbase, acc);

    const int tid = threadIdx.x, wid = tid >> 5, lane = tid & 31;
    const int wm = (wid >> 2) * 64, wn = (wid & 3) * 32;

    if (z < 2) {
        #pragma unroll
        for (int i = 0; i < 4; i++)
            #pragma unroll
            for (int j = 0; j < 4; j++)
                #pragma unroll
                for (int r = 0; r < 4; r++) {
                    int rr = row0 + wm + i * 16 + (lane >> 2) + 8 * (r >> 1);
                    int cc = col0 + wn + j * 8 + 2 * (lane & 3) + (r & 1);
                    float v = acc[i][j][r] + bias[cc];
                    if (z == 0) split2(v, g_qh[(size_t)rr * DIMN + cc], g_ql[(size_t)rr * DIMN + cc]);
                    else        split2(v * SCALE, g_kh[(size_t)rr * DIMN + cc], g_kl[(size_t)rr * DIMN + cc]);
                }
    } else {
        // V: transpose through smem, then coalesced packed fp16 stores
        __syncthreads();
        float* tsm = (float*)dsm;              // [128][132]
        #pragma unroll
        for (int i = 0; i < 4; i++)
            #pragma unroll
            for (int j = 0; j < 4; j++)
                #pragma unroll
                for (int r = 0; r < 4; r++) {
                    int lrr = wm + i * 16 + (lane >> 2) + 8 * (r >> 1);
                    int lcc = wn + j * 8 + 2 * (lane & 3) + (r & 1);
                    tsm[lcc * 132 + lrr] = acc[i][j][r] + bias[col0 + lcc];
                }
        __syncthreads();
        #pragma unroll
        for (int it = 0; it < 8; it++) {
            int idx = it * 256 + tid;
            int vr = idx >> 4;
            int c8 = (idx & 15) * 8;
            uint32_t hw[4], lw[4];
            #pragma unroll
            for (int m = 0; m < 4; m++) {
                float v0 = tsm[vr * 132 + c8 + 2 * m];
                float v1 = tsm[vr * 132 + c8 + 2 * m + 1];
                __half h0, l0, h1, l1;
                split2h(v0, h0, l0);
                split2h(v1, h1, l1);
                hw[m] = pack_h2(h0, h1);
                lw[m] = pack_h2(l0, l1);
            }
            size_t base = (size_t)(col0 + vr) * SQ + row0 + c8;
            *(uint4*)(g_vth + base) = make_uint4(hw[0], hw[1], hw[2], hw[3]);
            *(uint4*)(g_vtl + base) = make_uint4(lw[0], lw[1], lw[2], lw[3]);
        }
    }
}

// ---------------------------------------------------------------------------
// Raw causal scores (SCALE pre-folded into K). grid (64, 64).
// ---------------------------------------------------------------------------
__global__ __launch_bounds__(256, 2) void scores_mma_kernel(float* __restrict__ attn)
{
    const int bi = blockIdx.y, bj = blockIdx.x;
    const int row0 = bi * 128, col0 = bj * 128;

    if (bj > bi) {
        float4 z = make_float4(0.f, 0.f, 0.f, 0.f);
        #pragma unroll 4
        for (int idx = threadIdx.x; idx < 128 * 32; idx += 256) {
            int r = idx >> 5, c = (idx & 31) << 2;
            *(float4*)(attn + (size_t)(row0 + r) * SQ + col0 + c) = z;
        }
        return;
    }

    extern __shared__ __align__(16) char dsm[];
    uint32_t sbase = smem_u32(dsm);

    float acc[4][4][4];
    #pragma unroll
    for (int i = 0; i < 4; i++)
        #pragma unroll
        for (int j = 0; j < 4; j++)
            #pragma unroll
            for (int r = 0; r < 4; r++) acc[i][j][r] = 0.f;

    run_gemm(g_qh + (size_t)row0 * DIMN, g_ql + (size_t)row0 * DIMN, DIMN,
             g_kh + (size_t)col0 * DIMN, g_kl + (size_t)col0 * DIMN, DIMN,
             DIMN / KCHUNK, sbase, acc);

    const int tid = threadIdx.x, wid = tid >> 5, lane = tid & 31;
    const int wm = (wid >> 2) * 64, wn = (wid & 3) * 32;
    const bool diag = (bi == bj);
    #pragma unroll
    for (int i = 0; i < 4; i++)
        #pragma unroll
        for (int j = 0; j < 4; j++)
            #pragma unroll
            for (int rh = 0; rh < 2; rh++) {
                int rr = row0 + wm + i * 16 + (lane >> 2) + 8 * rh;
                int cc = col0 + wn + j * 8 + 2 * (lane & 3);
                float2 v;
                v.x = acc[i][j][2 * rh + 0];
                v.y = acc[i][j][2 * rh + 1];
                if (diag) {
                    if (cc + 0 > rr) v.x = 0.f;
                    if (cc + 1 > rr) v.y = 0.f;
                }
                *(float2*)(attn + (size_t)rr * SQ + cc) = v;
            }
}

// ---------------------------------------------------------------------------
// Causal softmax in place + emit fp16 weights for AV. Vectorized.
// ---------------------------------------------------------------------------
__global__ __launch_bounds__(256) void softmax_kernel(float* __restrict__ attn)
{
    __shared__ __align__(16) float buf[SQ];
    __shared__ float red[32];
    __shared__ float s_bcast;

    const int i = blockIdx.x;
    const int L = i + 1;
    const int L4 = L >> 2;
    const int tail = L & 3;
    float* row = attn + (size_t)i * SQ;
    const int tid = threadIdx.x;

    float mx = -3.4e38f;
    for (int j4 = tid; j4 < L4; j4 += 256) {
        float4 s = ((const float4*)row)[j4];
        ((float4*)buf)[j4] = s;
        mx = fmaxf(fmaxf(mx, fmaxf(s.x, s.y)), fmaxf(s.z, s.w));
    }
    if (tid < tail) {
        int j = L4 * 4 + tid;
        float s = row[j];
        buf[j] = s;
        mx = fmaxf(mx, s);
    }
    #pragma unroll
    for (int o = 16; o; o >>= 1) mx = fmaxf(mx, __shfl_xor_sync(0xffffffffu, mx, o));
    if ((tid & 31) == 0) red[tid >> 5] = mx;
    __syncthreads();
    if (tid < 32) {
        float v = (tid < 8) ? red[tid] : -3.4e38f;
        #pragma unroll
        for (int o = 4; o; o >>= 1) v = fmaxf(v, __shfl_xor_sync(0xffffffffu, v, o));
        if (tid == 0) s_bcast = v;
    }
    __syncthreads();
    mx = s_bcast;

    float sum = 0.f;
    for (int j4 = tid; j4 < L4; j4 += 256) {
        float4 e = ((const float4*)buf)[j4];
        e.x = __expf(e.x - mx); e.y = __expf(e.y - mx);
        e.z = __expf(e.z - mx); e.w = __expf(e.w - mx);
        ((float4*)buf)[j4] = e;
        sum += (e.x + e.y) + (e.z + e.w);
    }
    if (tid < tail) {
        int j = L4 * 4 + tid;
        float e = __expf(buf[j] - mx);
        buf[j] = e;
        sum += e;
    }
    #pragma unroll
    for (int o = 16; o; o >>= 1) sum += __shfl_xor_sync(0xffffffffu, sum, o);
    __syncthreads();
    if ((tid & 31) == 0) red[tid >> 5] = sum;
    __syncthreads();
    if (tid < 32) {
        float v = (tid < 8) ? red[tid] : 0.f;
        #pragma unroll
        for (int o = 4; o; o >>= 1) v += __shfl_xor_sync(0xffffffffu, v, o);
        if (tid == 0) s_bcast = 1.f / v;
    }
    __syncthreads();
    const float inv = s_bcast;

    __half* aw = g_aw + (size_t)i * SQ;
    for (int j4 = tid; j4 < L4; j4 += 256) {
        float4 w = ((const float4*)buf)[j4];
        w.x *= inv; w.y *= inv; w.z *= inv; w.w *= inv;
        ((float4*)row)[j4] = w;
        uint2 hw;
        hw.x = pack_h2(__float2half_rn(w.x), __float2half_rn(w.y));
        hw.y = pack_h2(__float2half_rn(w.z), __float2half_rn(w.w));
        *(uint2*)(aw + j4 * 4) = hw;
    }
    if (tid < tail) {
        int j = L4 * 4 + tid;
        float w = buf[j] * inv;
        row[j] = w;
        aw[j] = __float2half_rn(w);
    }
}

// ---------------------------------------------------------------------------
// output = attn(fp16) @ V(fp16 split), uniform split-K units. grid (4, 64, 8).
// ---------------------------------------------------------------------------
__global__ __launch_bounds__(256, 2) void av_mma_kernel(float* __restrict__ out)
{
    const int bn = blockIdx.x, bm = blockIdx.y, seg = blockIdx.z;
    const int nseg = (bm + 8) >> 3;
    if (seg >= nseg) return;

    const int row0 = bm * 128, col0 = bn * 128;
    const int k0 = seg * 1024;
    const int ktot = (bm + 1) * 128;
    const int kend = (k0 + 1024 < ktot) ? (k0 + 1024) : ktot;
    const int nchunks = (kend - k0) / KCHUNK;

    extern __shared__ __align__(16) char dsm[];
    uint32_t sbase = smem_u32(dsm);

    float acc[4][4][4];
    #pragma unroll
    for (int i = 0; i < 4; i++)
        #pragma unroll
        for (int j = 0; j < 4; j++)
            #pragma unroll
            for (int r = 0; r < 4; r++) acc[i][j][r] = 0.f;

    run_gemm_av(g_aw + (size_t)row0 * SQ + k0, SQ,
                g_vth + (size_t)col0 * SQ + k0, g_vtl + (size_t)col0 * SQ + k0, SQ,
                nchunks, sbase, acc);

    const int tid = threadIdx.x, wid = tid >> 5, lane = tid & 31;
    const int wm = (wid >> 2) * 64, wn = (wid & 3) * 32;

    if (nseg == 1) {
        #pragma unroll
        for (int i = 0; i < 4; i++)
            #pragma unroll
            for (int j = 0; j < 4; j++)
                #pragma unroll
                for (int rh = 0; rh < 2; rh++) {
                    int rr = row0 + wm + i * 16 + (lane >> 2) + 8 * rh;
                    int cc = col0 + wn + j * 8 + 2 * (lane & 3);
                    float2 v;
                    v.x = acc[i][j][2 * rh + 0];
                    v.y = acc[i][j][2 * rh + 1];
                    *(float2*)(out + (size_t)rr * DIMN + cc) = v;
                }
    } else {
        float* slot = g_part + ((size_t)((bm * 4 + bn) * 8 + seg)) * 16384;
        #pragma unroll
        for (int i = 0; i < 4; i++)
            #pragma unroll
            for (int j = 0; j < 4; j++)
                #pragma unroll
                for (int rh = 0; rh < 2; rh++) {
                    int lrr = wm + i * 16 + (lane >> 2) + 8 * rh;
                    int lcc = wn + j * 8 + 2 * (lane & 3);
                    float2 v;
                    v.x = acc[i][j][2 * rh + 0];
                    v.y = acc[i][j][2 * rh + 1];
                    *(float2*)(slot + lrr * 128 + lcc) = v;
                }
    }
}

// ---------------------------------------------------------------------------
__global__ __launch_bounds__(256) void av_reduce_kernel(float* __restrict__ out)
{
    const int bn = blockIdx.x, bm = 8 + blockIdx.y;
    const int nseg = (bm + 8) >> 3;
    const int row0 = bm * 128, col0 = bn * 128;
    const float* base = g_part + ((size_t)((bm * 4 + bn) * 8)) * 16384;

    for (int idx = threadIdx.x; idx < 4096; idx += 256) {
        float4 s = *(const float4*)(base + idx * 4);
        for (int sg = 1; sg < nseg; sg++) {
            float4 p = *(const float4*)(base + (size_t)sg * 16384 + idx * 4);
            s.x += p.x; s.y += p.y; s.z += p.z; s.w += p.w;
        }
        int lr = idx >> 5, lc = (idx & 31) << 2;
        *(float4*)(out + (size_t)(row0 + lr) * DIMN + col0 + lc) = s;
    }
}

// ---------------------------------------------------------------------------
extern "C" void kernel_launch(void* const* d_in, const int* in_sizes, int n_in,
                              void* d_out, int out_size)
{
    const float* x  = (const float*)d_in[0];
    const float* Wq = (const float*)d_in[1];
    const float* bq = (const float*)d_in[2];
    const float* Wk = (const float*)d_in[3];
    const float* bk = (const float*)d_in[4];
    const float* Wv = (const float*)d_in[5];
    const float* bv = (const float*)d_in[6];

    float* out  = (float*)d_out;                 // [S, D]
    float* attn = out + (size_t)SQ * DIMN;       // [S, S]

    const int SMEM_BYTES    = NSTAGE * (int)STAGE_BYTES;        // 96 KB
    const int AV_SMEM_BYTES = AV_NSTAGE * (int)AV_STAGE_BYTES;  // 96 KB
    cudaFuncSetAttribute(qkv_mma_kernel,    cudaFuncAttributeMaxDynamicSharedMemorySize, SMEM_BYTES);
    cudaFuncSetAttribute(scores_mma_kernel, cudaFuncAttributeMaxDynamicSharedMemorySize, SMEM_BYTES);
    cudaFuncSetAttribute(av_mma_kernel,     cudaFuncAttributeMaxDynamicSharedMemorySize, AV_SMEM_BYTES);

    conv_kernel<<<(SQ * DIMN) / 256, 256>>>(x, Wq, Wk, Wv);

    dim3 g_qkv(DIMN / 128, SQ / 128, 3);
    qkv_mma_kernel<<<g_qkv, 256, SMEM_BYTES>>>(bq, bk, bv);

    dim3 g_sc(SQ / 128, SQ / 128);
    scores_mma_kernel<<<g_sc, 256, SMEM_BYTES>>>(attn);

    softmax_kernel<<<SQ, 256>>>(attn);

    dim3 g_av(4, 64, 8);
    av_mma_kernel<<<g_av, 256, AV_SMEM_BYTES>>>(out);

    dim3 g_red(4, 56);
    av_reduce_kernel<<<g_red, 256>>>(out);
}